// round 2
// baseline (speedup 1.0000x reference)
#include <cuda_runtime.h>
#include <cuda_bf16.h>

// Problem dims
#define Bz  2
#define Sz  1024
#define Dz  2048
#define Hz  16
#define DHz 128
#define DFFz 8192

// ---------------------------------------------------------------------------
// Scratch (device globals; no allocation allowed)
// ---------------------------------------------------------------------------
__device__ float g_q [Bz*Hz*Sz*DHz];     // [b,h,s,e]
__device__ float g_k [Bz*Hz*Sz*DHz];
__device__ float g_v [Bz*Hz*Sz*DHz];
__device__ float g_sc[(long)Bz*Hz*Sz*Sz]; // scores / attn, [b,h,q,k]
__device__ float g_cat[Bz*Sz*Dz];        // concatenated heads [b,s,h*e]
__device__ float g_tmp[Bz*Sz*Dz];        // proj / ffn output before LN
__device__ float g_x1[Bz*Sz*Dz];
__device__ float g_x2[Bz*Sz*Dz];
__device__ float g_ff[Bz*Sz*DFFz];

// ---------------------------------------------------------------------------
// Packed f32x2 helpers (Blackwell FFMA2 path)
// ---------------------------------------------------------------------------
__device__ __forceinline__ unsigned long long pk2(float lo, float hi) {
    unsigned long long r;
    asm("mov.b64 %0, {%1, %2};" : "=l"(r) : "f"(lo), "f"(hi));
    return r;
}
__device__ __forceinline__ void upk2(unsigned long long v, float& lo, float& hi) {
    asm("mov.b64 {%0, %1}, %2;" : "=f"(lo), "=f"(hi) : "l"(v));
}
__device__ __forceinline__ void ffma2(unsigned long long& d, unsigned long long a, unsigned long long b) {
    asm("fma.rn.f32x2 %0, %1, %2, %0;" : "+l"(d) : "l"(a), "l"(b));
}

// ---------------------------------------------------------------------------
// Generic 128x128 tile GEMM body. A row-major [M,K] (lda), B row-major [K,N]
// (ldb) or, if TRANSB, B is [N,K] (ldb) and we compute A*B^T.
// Block computes tile (blockIdx.x*128, blockIdx.y*128). All dims assumed
// multiples of the tile sizes (true for every shape in this problem).
// C[m,n] = alpha * sum_k A.. * B.. (+ bias[n]) (relu optional)
// ---------------------------------------------------------------------------
template<bool TRANSB>
__device__ __forceinline__ void gemm_body(
    const float* __restrict__ A, int lda,
    const float* __restrict__ Bm, int ldb,
    const float* __restrict__ bias,
    float* __restrict__ C, int ldc,
    int K, float alpha, bool relu)
{
    __shared__ float As[16][132];
    __shared__ float Bs[16][132];
    const int tid = threadIdx.x;
    const int m0 = blockIdx.x * 128;
    const int n0 = blockIdx.y * 128;
    const int tm = (tid >> 4) << 3;   // 0..120
    const int tn = (tid & 15) << 3;   // 0..120

    unsigned long long acc[8][4];
#pragma unroll
    for (int i = 0; i < 8; i++)
#pragma unroll
        for (int j = 0; j < 4; j++) acc[i][j] = 0ULL;   // (0.f,0.f)

    for (int k0 = 0; k0 < K; k0 += 16) {
        // --- load A tile [128 rows x 16 k] transposed into As[k][m]
#pragma unroll
        for (int t = 0; t < 2; t++) {
            int idx = tid + t * 256;            // 0..511
            int row = idx >> 2;                 // 0..127
            int c4  = (idx & 3) << 2;           // 0,4,8,12
            float4 av = *(const float4*)(A + (long)(m0 + row) * lda + (k0 + c4));
            As[c4 + 0][row] = av.x;
            As[c4 + 1][row] = av.y;
            As[c4 + 2][row] = av.z;
            As[c4 + 3][row] = av.w;
        }
        // --- load B tile into Bs[k][n]
        if (!TRANSB) {
#pragma unroll
            for (int t = 0; t < 2; t++) {
                int idx = tid + t * 256;
                int kk = idx >> 5;              // 0..15
                int n4 = (idx & 31) << 2;       // 0..124
                *(float4*)&Bs[kk][n4] =
                    *(const float4*)(Bm + (long)(k0 + kk) * ldb + (n0 + n4));
            }
        } else {
#pragma unroll
            for (int t = 0; t < 2; t++) {
                int idx = tid + t * 256;
                int nn = idx >> 2;              // 0..127
                int c4 = (idx & 3) << 2;
                float4 bv = *(const float4*)(Bm + (long)(n0 + nn) * ldb + (k0 + c4));
                Bs[c4 + 0][nn] = bv.x;
                Bs[c4 + 1][nn] = bv.y;
                Bs[c4 + 2][nn] = bv.z;
                Bs[c4 + 3][nn] = bv.w;
            }
        }
        __syncthreads();

#pragma unroll
        for (int kk = 0; kk < 16; kk++) {
            float4 a0 = *(const float4*)&As[kk][tm];
            float4 a1 = *(const float4*)&As[kk][tm + 4];
            float4 b0 = *(const float4*)&Bs[kk][tn];
            float4 b1 = *(const float4*)&Bs[kk][tn + 4];
            unsigned long long bb0 = pk2(b0.x, b0.y);
            unsigned long long bb1 = pk2(b0.z, b0.w);
            unsigned long long bb2 = pk2(b1.x, b1.y);
            unsigned long long bb3 = pk2(b1.z, b1.w);
            float av[8] = {a0.x, a0.y, a0.z, a0.w, a1.x, a1.y, a1.z, a1.w};
#pragma unroll
            for (int i = 0; i < 8; i++) {
                unsigned long long aa = pk2(av[i], av[i]);
                ffma2(acc[i][0], aa, bb0);
                ffma2(acc[i][1], aa, bb1);
                ffma2(acc[i][2], aa, bb2);
                ffma2(acc[i][3], aa, bb3);
            }
        }
        __syncthreads();
    }

    // --- epilogue
#pragma unroll
    for (int i = 0; i < 8; i++) {
        float v[8];
        upk2(acc[i][0], v[0], v[1]);
        upk2(acc[i][1], v[2], v[3]);
        upk2(acc[i][2], v[4], v[5]);
        upk2(acc[i][3], v[6], v[7]);
        int row = m0 + tm + i;
#pragma unroll
        for (int j = 0; j < 8; j++) {
            float o = v[j] * alpha;
            if (bias) o += bias[n0 + tn + j];
            if (relu) o = fmaxf(o, 0.0f);
            v[j] = o;
        }
        long base = (long)row * ldc + n0 + tn;
        *(float4*)(C + base)     = make_float4(v[0], v[1], v[2], v[3]);
        *(float4*)(C + base + 4) = make_float4(v[4], v[5], v[6], v[7]);
    }
}

// ---------------------------------------------------------------------------
// Kernels
// ---------------------------------------------------------------------------

// Per-head projection: out[(b*H+h)*S + s, e] = sum_d in[b*S+s, d]*w[h, d, e] + bias[h, e]
// grid (S/128=8, 1, B*H=32)
__global__ void __launch_bounds__(256)
proj_kernel(const float* __restrict__ in, const float* __restrict__ w,
            const float* __restrict__ bias, float* __restrict__ out)
{
    int z = blockIdx.z;
    int b = z >> 4;          // /H
    int h = z & 15;          // %H
    gemm_body<false>(in + (long)b * Sz * Dz, Dz,
                     w + (long)h * Dz * DHz, DHz,
                     bias + h * DHz,
                     out + (long)z * Sz * DHz, DHz,
                     Dz, 1.0f, false);
}

// scores[z, q, k] = (1/sqrt(DH)) * sum_e Q[z,q,e] * K[z,k,e]   grid (8,8,32)
__global__ void __launch_bounds__(256)
scores_kernel(const float* __restrict__ q, const float* __restrict__ kb,
              float* __restrict__ sc)
{
    int z = blockIdx.z;
    gemm_body<true>(q + (long)z * Sz * DHz, DHz,
                    kb + (long)z * Sz * DHz, DHz,
                    nullptr,
                    sc + (long)z * Sz * Sz, Sz,
                    DHz, 0.08838834764831845f, false);
}

// Softmax over the QUERY axis (column softmax of each SxS matrix). grid (S/256, B*H)
__global__ void __launch_bounds__(256)
softmax_q_kernel(float* __restrict__ sc)
{
    long base = (long)blockIdx.y * Sz * Sz;
    int kcol = blockIdx.x * 256 + threadIdx.x;
    float* p = sc + base + kcol;
    float mx = -1e30f;
    for (int qq = 0; qq < Sz; qq++) mx = fmaxf(mx, p[(long)qq * Sz]);
    float sum = 0.f;
    for (int qq = 0; qq < Sz; qq++) sum += __expf(p[(long)qq * Sz] - mx);
    float inv = 1.0f / sum;
    for (int qq = 0; qq < Sz; qq++) {
        long o = (long)qq * Sz;
        p[o] = __expf(p[o] - mx) * inv;
    }
}

// out_cat[b*S+q, h*DH+e] = sum_k attn[z,q,k] * V[z,k,e]    grid (8,1,32)
__global__ void __launch_bounds__(256)
attnv_kernel(const float* __restrict__ sc, const float* __restrict__ v,
             float* __restrict__ cat)
{
    int z = blockIdx.z;
    int b = z >> 4;
    int h = z & 15;
    gemm_body<false>(sc + (long)z * Sz * Sz, Sz,
                     v + (long)z * Sz * DHz, DHz,
                     nullptr,
                     cat + (long)b * Sz * Dz + h * DHz, Dz,
                     Sz, 1.0f, false);
}

// Plain GEMM: C[M,N] = A[M,K] @ B[K,N] + bias (+relu).  grid (M/128, N/128)
__global__ void __launch_bounds__(256)
gemm_nn_kernel(const float* __restrict__ A, const float* __restrict__ Bm,
               const float* __restrict__ bias, float* __restrict__ C,
               int K, int N, int relu)
{
    gemm_body<false>(A, K, Bm, N, bias, C, N, K, 1.0f, relu != 0);
}

// out = LayerNorm(xa + xb) * g + b, rowwise over D. grid = B*S, 256 threads.
__global__ void __launch_bounds__(256)
add_ln_kernel(const float* __restrict__ xa, const float* __restrict__ xb,
              const float* __restrict__ gg, const float* __restrict__ bb,
              float* __restrict__ out)
{
    int row = blockIdx.x;
    const float* xr = xa + (long)row * Dz;
    const float* yr = xb + (long)row * Dz;
    float v[8];
    float s = 0.f, s2 = 0.f;
#pragma unroll
    for (int i = 0; i < 8; i++) {
        int c = threadIdx.x + i * 256;
        v[i] = xr[c] + yr[c];
        s += v[i];
        s2 += v[i] * v[i];
    }
    __shared__ float rs[8], rs2[8];
#pragma unroll
    for (int o = 16; o > 0; o >>= 1) {
        s  += __shfl_xor_sync(0xffffffffu, s, o);
        s2 += __shfl_xor_sync(0xffffffffu, s2, o);
    }
    int wid = threadIdx.x >> 5, lid = threadIdx.x & 31;
    if (lid == 0) { rs[wid] = s; rs2[wid] = s2; }
    __syncthreads();
    if (threadIdx.x < 32) {
        s  = (threadIdx.x < 8) ? rs[threadIdx.x]  : 0.f;
        s2 = (threadIdx.x < 8) ? rs2[threadIdx.x] : 0.f;
#pragma unroll
        for (int o = 4; o > 0; o >>= 1) {
            s  += __shfl_xor_sync(0xffffffffu, s, o);
            s2 += __shfl_xor_sync(0xffffffffu, s2, o);
        }
        if (threadIdx.x == 0) { rs[0] = s; rs2[0] = s2; }
    }
    __syncthreads();
    float mean = rs[0] * (1.0f / Dz);
    float var  = rs2[0] * (1.0f / Dz) - mean * mean;
    float inv  = rsqrtf(var + 1e-5f);
    float* orow = out + (long)row * Dz;
#pragma unroll
    for (int i = 0; i < 8; i++) {
        int c = threadIdx.x + i * 256;
        orow[c] = (v[i] - mean) * inv * gg[c] + bb[c];
    }
}

// ---------------------------------------------------------------------------
// Launch
// ---------------------------------------------------------------------------
extern "C" void kernel_launch(void* const* d_in, const int* in_sizes, int n_in,
                              void* d_out, int out_size)
{
    const float* x    = (const float*)d_in[0];
    const float* enc  = (const float*)d_in[1];
    const float* wq1  = (const float*)d_in[2];
    const float* wk1  = (const float*)d_in[3];
    const float* wv1  = (const float*)d_in[4];
    const float* bq1  = (const float*)d_in[5];
    const float* bk1  = (const float*)d_in[6];
    const float* bv1  = (const float*)d_in[7];
    const float* wp1  = (const float*)d_in[8];
    const float* bp1  = (const float*)d_in[9];
    const float* wq2  = (const float*)d_in[10];
    const float* wk2  = (const float*)d_in[11];
    const float* wv2  = (const float*)d_in[12];
    const float* bq2  = (const float*)d_in[13];
    const float* bk2  = (const float*)d_in[14];
    const float* bv2  = (const float*)d_in[15];
    const float* wp2  = (const float*)d_in[16];
    const float* bp2  = (const float*)d_in[17];
    const float* ln1g = (const float*)d_in[18];
    const float* ln1b = (const float*)d_in[19];
    const float* ln2g = (const float*)d_in[20];
    const float* ln2b = (const float*)d_in[21];
    const float* ln3g = (const float*)d_in[22];
    const float* ln3b = (const float*)d_in[23];
    const float* wff1 = (const float*)d_in[24];
    const float* bff1 = (const float*)d_in[25];
    const float* wff2 = (const float*)d_in[26];
    const float* bff2 = (const float*)d_in[27];
    float* out = (float*)d_out;

    float *q, *k, *v, *sc, *cat, *tmp, *x1, *x2, *ff;
    cudaGetSymbolAddress((void**)&q,   g_q);
    cudaGetSymbolAddress((void**)&k,   g_k);
    cudaGetSymbolAddress((void**)&v,   g_v);
    cudaGetSymbolAddress((void**)&sc,  g_sc);
    cudaGetSymbolAddress((void**)&cat, g_cat);
    cudaGetSymbolAddress((void**)&tmp, g_tmp);
    cudaGetSymbolAddress((void**)&x1,  g_x1);
    cudaGetSymbolAddress((void**)&x2,  g_x2);
    cudaGetSymbolAddress((void**)&ff,  g_ff);

    dim3 blk(256);
    dim3 gproj(Sz / 128, 1, Bz * Hz);          // (8,1,32)
    dim3 gsc(Sz / 128, Sz / 128, Bz * Hz);     // (8,8,32)
    dim3 gsm(Sz / 256, Bz * Hz);               // (4,32)
    dim3 gpp(2 * Sz / 128, Dz / 128);          // (16,16)
    dim3 gff1(2 * Sz / 128, DFFz / 128);       // (16,64)

    // ---- self attention ----
    proj_kernel<<<gproj, blk>>>(x, wq1, bq1, q);
    proj_kernel<<<gproj, blk>>>(x, wk1, bk1, k);
    proj_kernel<<<gproj, blk>>>(x, wv1, bv1, v);
    scores_kernel<<<gsc, blk>>>(q, k, sc);
    softmax_q_kernel<<<gsm, blk>>>(sc);
    attnv_kernel<<<gproj, blk>>>(sc, v, cat);
    gemm_nn_kernel<<<gpp, blk>>>(cat, wp1, bp1, tmp, Dz, Dz, 0);
    add_ln_kernel<<<Bz * Sz, blk>>>(x, tmp, ln1g, ln1b, x1);

    // ---- cross attention: q from encoder_output, k/v from x1 ----
    proj_kernel<<<gproj, blk>>>(enc, wq2, bq2, q);
    proj_kernel<<<gproj, blk>>>(x1, wk2, bk2, k);
    proj_kernel<<<gproj, blk>>>(x1, wv2, bv2, v);
    scores_kernel<<<gsc, blk>>>(q, k, sc);
    softmax_q_kernel<<<gsm, blk>>>(sc);
    attnv_kernel<<<gproj, blk>>>(sc, v, cat);
    gemm_nn_kernel<<<gpp, blk>>>(cat, wp2, bp2, tmp, Dz, Dz, 0);
    add_ln_kernel<<<Bz * Sz, blk>>>(x1, tmp, ln2g, ln2b, x2);

    // ---- feed forward ----
    gemm_nn_kernel<<<gff1, blk>>>(x2, wff1, bff1, ff, Dz, DFFz, 1);
    gemm_nn_kernel<<<gpp, blk>>>(ff, wff2, bff2, tmp, DFFz, Dz, 0);
    add_ln_kernel<<<Bz * Sz, blk>>>(x2, tmp, ln3g, ln3b, out);
}

// round 4
// speedup vs baseline: 1.6141x; 1.6141x over previous
#include <cuda_runtime.h>
#include <cuda_bf16.h>

// Problem dims
#define Bz  2
#define Sz  1024
#define Dz  2048
#define Hz  16
#define DHz 128
#define DFFz 8192

// ---------------------------------------------------------------------------
// Scratch (device globals; no allocation allowed)
// ---------------------------------------------------------------------------
__device__ float g_q [Bz*Hz*Sz*DHz];     // [b,h,s,e]
__device__ float g_k [Bz*Hz*Sz*DHz];
__device__ float g_v [Bz*Hz*Sz*DHz];
__device__ float g_sc[(long)Bz*Hz*Sz*Sz]; // scores / attn, [b,h,q,k]
__device__ float g_cat[Bz*Sz*Dz];        // concatenated heads [b,s,h*e]
__device__ float g_tmp[Bz*Sz*Dz];        // proj / ffn output before LN
__device__ float g_x1[Bz*Sz*Dz];
__device__ float g_x2[Bz*Sz*Dz];
__device__ float g_ff[Bz*Sz*DFFz];

// ---------------------------------------------------------------------------
// Packed f32x2 helpers (Blackwell FFMA2 path)
// ---------------------------------------------------------------------------
__device__ __forceinline__ unsigned long long pk2(float lo, float hi) {
    unsigned long long r;
    asm("mov.b64 %0, {%1, %2};" : "=l"(r) : "f"(lo), "f"(hi));
    return r;
}
__device__ __forceinline__ void upk2(unsigned long long v, float& lo, float& hi) {
    asm("mov.b64 {%0, %1}, %2;" : "=f"(lo), "=f"(hi) : "l"(v));
}
__device__ __forceinline__ void ffma2(unsigned long long& d, unsigned long long a, unsigned long long b) {
    asm("fma.rn.f32x2 %0, %1, %2, %0;" : "+l"(d) : "l"(a), "l"(b));
}

// ---------------------------------------------------------------------------
// Generic 128x128 tile GEMM body. A row-major [M,K] (lda), B row-major [K,N]
// (ldb) or, if TRANSB, B is [N,K] (ldb) and we compute A*B^T.
// Block computes tile (blockIdx.x*128, blockIdx.y*128). All dims assumed
// multiples of the tile sizes (true for every shape in this problem).
// C[m,n] = alpha * sum_k A.. * B.. (+ bias[n]) (relu optional)
// ---------------------------------------------------------------------------
template<bool TRANSB>
__device__ __forceinline__ void gemm_body(
    const float* __restrict__ A, int lda,
    const float* __restrict__ Bm, int ldb,
    const float* __restrict__ bias,
    float* __restrict__ C, int ldc,
    int K, float alpha, bool relu)
{
    __shared__ float As[16][132];
    __shared__ float Bs[16][132];
    const int tid = threadIdx.x;
    const int m0 = blockIdx.x * 128;
    const int n0 = blockIdx.y * 128;
    const int tm = (tid >> 4) << 3;   // 0..120
    const int tn = (tid & 15) << 3;   // 0..120

    unsigned long long acc[8][4];
#pragma unroll
    for (int i = 0; i < 8; i++)
#pragma unroll
        for (int j = 0; j < 4; j++) acc[i][j] = 0ULL;   // (0.f,0.f)

    for (int k0 = 0; k0 < K; k0 += 16) {
        // --- load A tile [128 rows x 16 k] transposed into As[k][m]
#pragma unroll
        for (int t = 0; t < 2; t++) {
            int idx = tid + t * 256;            // 0..511
            int row = idx >> 2;                 // 0..127
            int c4  = (idx & 3) << 2;           // 0,4,8,12
            float4 av = *(const float4*)(A + (long)(m0 + row) * lda + (k0 + c4));
            As[c4 + 0][row] = av.x;
            As[c4 + 1][row] = av.y;
            As[c4 + 2][row] = av.z;
            As[c4 + 3][row] = av.w;
        }
        // --- load B tile into Bs[k][n]
        if (!TRANSB) {
#pragma unroll
            for (int t = 0; t < 2; t++) {
                int idx = tid + t * 256;
                int kk = idx >> 5;              // 0..15
                int n4 = (idx & 31) << 2;       // 0..124
                *(float4*)&Bs[kk][n4] =
                    *(const float4*)(Bm + (long)(k0 + kk) * ldb + (n0 + n4));
            }
        } else {
#pragma unroll
            for (int t = 0; t < 2; t++) {
                int idx = tid + t * 256;
                int nn = idx >> 2;              // 0..127
                int c4 = (idx & 3) << 2;
                float4 bv = *(const float4*)(Bm + (long)(n0 + nn) * ldb + (k0 + c4));
                Bs[c4 + 0][nn] = bv.x;
                Bs[c4 + 1][nn] = bv.y;
                Bs[c4 + 2][nn] = bv.z;
                Bs[c4 + 3][nn] = bv.w;
            }
        }
        __syncthreads();

#pragma unroll
        for (int kk = 0; kk < 16; kk++) {
            float4 a0 = *(const float4*)&As[kk][tm];
            float4 a1 = *(const float4*)&As[kk][tm + 4];
            float4 b0 = *(const float4*)&Bs[kk][tn];
            float4 b1 = *(const float4*)&Bs[kk][tn + 4];
            unsigned long long bb0 = pk2(b0.x, b0.y);
            unsigned long long bb1 = pk2(b0.z, b0.w);
            unsigned long long bb2 = pk2(b1.x, b1.y);
            unsigned long long bb3 = pk2(b1.z, b1.w);
            float av[8] = {a0.x, a0.y, a0.z, a0.w, a1.x, a1.y, a1.z, a1.w};
#pragma unroll
            for (int i = 0; i < 8; i++) {
                unsigned long long aa = pk2(av[i], av[i]);
                ffma2(acc[i][0], aa, bb0);
                ffma2(acc[i][1], aa, bb1);
                ffma2(acc[i][2], aa, bb2);
                ffma2(acc[i][3], aa, bb3);
            }
        }
        __syncthreads();
    }

    // --- epilogue
#pragma unroll
    for (int i = 0; i < 8; i++) {
        float v[8];
        upk2(acc[i][0], v[0], v[1]);
        upk2(acc[i][1], v[2], v[3]);
        upk2(acc[i][2], v[4], v[5]);
        upk2(acc[i][3], v[6], v[7]);
        int row = m0 + tm + i;
#pragma unroll
        for (int j = 0; j < 8; j++) {
            float o = v[j] * alpha;
            if (bias) o += bias[n0 + tn + j];
            if (relu) o = fmaxf(o, 0.0f);
            v[j] = o;
        }
        long base = (long)row * ldc + n0 + tn;
        *(float4*)(C + base)     = make_float4(v[0], v[1], v[2], v[3]);
        *(float4*)(C + base + 4) = make_float4(v[4], v[5], v[6], v[7]);
    }
}

// ---------------------------------------------------------------------------
// Kernels
// ---------------------------------------------------------------------------

// Per-head projection: out[(b*H+h)*S + s, e] = sum_d in[b*S+s, d]*w[h, d, e] + bias[h, e]
// grid (S/128=8, 1, B*H=32)
__global__ void __launch_bounds__(256)
proj_kernel(const float* __restrict__ in, const float* __restrict__ w,
            const float* __restrict__ bias, float* __restrict__ out)
{
    int z = blockIdx.z;
    int b = z >> 4;          // /H
    int h = z & 15;          // %H
    gemm_body<false>(in + (long)b * Sz * Dz, Dz,
                     w + (long)h * Dz * DHz, DHz,
                     bias + h * DHz,
                     out + (long)z * Sz * DHz, DHz,
                     Dz, 1.0f, false);
}

// scores[z, q, k] = (1/sqrt(DH)) * sum_e Q[z,q,e] * K[z,k,e]   grid (8,8,32)
__global__ void __launch_bounds__(256)
scores_kernel(const float* __restrict__ q, const float* __restrict__ kb,
              float* __restrict__ sc)
{
    int z = blockIdx.z;
    gemm_body<true>(q + (long)z * Sz * DHz, DHz,
                    kb + (long)z * Sz * DHz, DHz,
                    nullptr,
                    sc + (long)z * Sz * Sz, Sz,
                    DHz, 0.08838834764831845f, false);
}

// Softmax over the QUERY axis (column softmax of each SxS matrix). grid (S/256, B*H)
__global__ void __launch_bounds__(256)
softmax_q_kernel(float* __restrict__ sc)
{
    long base = (long)blockIdx.y * Sz * Sz;
    int kcol = blockIdx.x * 256 + threadIdx.x;
    float* p = sc + base + kcol;
    float mx = -1e30f;
    for (int qq = 0; qq < Sz; qq++) mx = fmaxf(mx, p[(long)qq * Sz]);
    float sum = 0.f;
    for (int qq = 0; qq < Sz; qq++) sum += __expf(p[(long)qq * Sz] - mx);
    float inv = 1.0f / sum;
    for (int qq = 0; qq < Sz; qq++) {
        long o = (long)qq * Sz;
        p[o] = __expf(p[o] - mx) * inv;
    }
}

// out_cat[b*S+q, h*DH+e] = sum_k attn[z,q,k] * V[z,k,e]    grid (8,1,32)
__global__ void __launch_bounds__(256)
attnv_kernel(const float* __restrict__ sc, const float* __restrict__ v,
             float* __restrict__ cat)
{
    int z = blockIdx.z;
    int b = z >> 4;
    int h = z & 15;
    gemm_body<false>(sc + (long)z * Sz * Sz, Sz,
                     v + (long)z * Sz * DHz, DHz,
                     nullptr,
                     cat + (long)b * Sz * Dz + h * DHz, Dz,
                     Sz, 1.0f, false);
}

// Plain GEMM: C[M,N] = A[M,K] @ B[K,N] + bias (+relu).  grid (M/128, N/128)
__global__ void __launch_bounds__(256)
gemm_nn_kernel(const float* __restrict__ A, const float* __restrict__ Bm,
               const float* __restrict__ bias, float* __restrict__ C,
               int K, int N, int relu)
{
    gemm_body<false>(A, K, Bm, N, bias, C, N, K, 1.0f, relu != 0);
}

// out = LayerNorm(xa + xb) * g + b, rowwise over D. grid = B*S, 256 threads.
__global__ void __launch_bounds__(256)
add_ln_kernel(const float* __restrict__ xa, const float* __restrict__ xb,
              const float* __restrict__ gg, const float* __restrict__ bb,
              float* __restrict__ out)
{
    int row = blockIdx.x;
    const float* xr = xa + (long)row * Dz;
    const float* yr = xb + (long)row * Dz;
    float v[8];
    float s = 0.f, s2 = 0.f;
#pragma unroll
    for (int i = 0; i < 8; i++) {
        int c = threadIdx.x + i * 256;
        v[i] = xr[c] + yr[c];
        s += v[i];
        s2 += v[i] * v[i];
    }
    __shared__ float rs[8], rs2[8];
#pragma unroll
    for (int o = 16; o > 0; o >>= 1) {
        s  += __shfl_xor_sync(0xffffffffu, s, o);
        s2 += __shfl_xor_sync(0xffffffffu, s2, o);
    }
    int wid = threadIdx.x >> 5, lid = threadIdx.x & 31;
    if (lid == 0) { rs[wid] = s; rs2[wid] = s2; }
    __syncthreads();
    if (threadIdx.x < 32) {
        s  = (threadIdx.x < 8) ? rs[threadIdx.x]  : 0.f;
        s2 = (threadIdx.x < 8) ? rs2[threadIdx.x] : 0.f;
#pragma unroll
        for (int o = 4; o > 0; o >>= 1) {
            s  += __shfl_xor_sync(0xffffffffu, s, o);
            s2 += __shfl_xor_sync(0xffffffffu, s2, o);
        }
        if (threadIdx.x == 0) { rs[0] = s; rs2[0] = s2; }
    }
    __syncthreads();
    float mean = rs[0] * (1.0f / Dz);
    float var  = rs2[0] * (1.0f / Dz) - mean * mean;
    float inv  = rsqrtf(var + 1e-5f);
    float* orow = out + (long)row * Dz;
#pragma unroll
    for (int i = 0; i < 8; i++) {
        int c = threadIdx.x + i * 256;
        orow[c] = (v[i] - mean) * inv * gg[c] + bb[c];
    }
}

// ---------------------------------------------------------------------------
// Launch
// ---------------------------------------------------------------------------
extern "C" void kernel_launch(void* const* d_in, const int* in_sizes, int n_in,
                              void* d_out, int out_size)
{
    const float* x    = (const float*)d_in[0];
    const float* enc  = (const float*)d_in[1];
    const float* wq1  = (const float*)d_in[2];
    const float* wk1  = (const float*)d_in[3];
    const float* wv1  = (const float*)d_in[4];
    const float* bq1  = (const float*)d_in[5];
    const float* bk1  = (const float*)d_in[6];
    const float* bv1  = (const float*)d_in[7];
    const float* wp1  = (const float*)d_in[8];
    const float* bp1  = (const float*)d_in[9];
    const float* wq2  = (const float*)d_in[10];
    const float* wk2  = (const float*)d_in[11];
    const float* wv2  = (const float*)d_in[12];
    const float* bq2  = (const float*)d_in[13];
    const float* bk2  = (const float*)d_in[14];
    const float* bv2  = (const float*)d_in[15];
    const float* wp2  = (const float*)d_in[16];
    const float* bp2  = (const float*)d_in[17];
    const float* ln1g = (const float*)d_in[18];
    const float* ln1b = (const float*)d_in[19];
    const float* ln2g = (const float*)d_in[20];
    const float* ln2b = (const float*)d_in[21];
    const float* ln3g = (const float*)d_in[22];
    const float* ln3b = (const float*)d_in[23];
    const float* wff1 = (const float*)d_in[24];
    const float* bff1 = (const float*)d_in[25];
    const float* wff2 = (const float*)d_in[26];
    const float* bff2 = (const float*)d_in[27];
    float* out = (float*)d_out;

    float *q, *k, *v, *sc, *cat, *tmp, *x1, *x2, *ff;
    cudaGetSymbolAddress((void**)&q,   g_q);
    cudaGetSymbolAddress((void**)&k,   g_k);
    cudaGetSymbolAddress((void**)&v,   g_v);
    cudaGetSymbolAddress((void**)&sc,  g_sc);
    cudaGetSymbolAddress((void**)&cat, g_cat);
    cudaGetSymbolAddress((void**)&tmp, g_tmp);
    cudaGetSymbolAddress((void**)&x1,  g_x1);
    cudaGetSymbolAddress((void**)&x2,  g_x2);
    cudaGetSymbolAddress((void**)&ff,  g_ff);

    dim3 blk(256);
    dim3 gproj(Sz / 128, 1, Bz * Hz);          // (8,1,32)
    dim3 gsc(Sz / 128, Sz / 128, Bz * Hz);     // (8,8,32)
    dim3 gsm(Sz / 256, Bz * Hz);               // (4,32)
    dim3 gpp(2 * Sz / 128, Dz / 128);          // (16,16)
    dim3 gff1(2 * Sz / 128, DFFz / 128);       // (16,64)

    // ---- self attention ----
    proj_kernel<<<gproj, blk>>>(x, wq1, bq1, q);
    proj_kernel<<<gproj, blk>>>(x, wk1, bk1, k);
    proj_kernel<<<gproj, blk>>>(x, wv1, bv1, v);
    scores_kernel<<<gsc, blk>>>(q, k, sc);
    softmax_q_kernel<<<gsm, blk>>>(sc);
    attnv_kernel<<<gproj, blk>>>(sc, v, cat);
    gemm_nn_kernel<<<gpp, blk>>>(cat, wp1, bp1, tmp, Dz, Dz, 0);
    add_ln_kernel<<<Bz * Sz, blk>>>(x, tmp, ln1g, ln1b, x1);

    // ---- cross attention: q from encoder_output, k/v from x1 ----
    proj_kernel<<<gproj, blk>>>(enc, wq2, bq2, q);
    proj_kernel<<<gproj, blk>>>(x1, wk2, bk2, k);
    proj_kernel<<<gproj, blk>>>(x1, wv2, bv2, v);
    scores_kernel<<<gsc, blk>>>(q, k, sc);
    softmax_q_kernel<<<gsm, blk>>>(sc);
    attnv_kernel<<<gproj, blk>>>(sc, v, cat);
    gemm_nn_kernel<<<gpp, blk>>>(cat, wp2, bp2, tmp, Dz, Dz, 0);
    add_ln_kernel<<<Bz * Sz, blk>>>(x1, tmp, ln2g, ln2b, x2);

    // ---- feed forward ----
    gemm_nn_kernel<<<gff1, blk>>>(x2, wff1, bff1, ff, Dz, DFFz, 1);
    gemm_nn_kernel<<<gpp, blk>>>(ff, wff2, bff2, tmp, DFFz, Dz, 0);
    add_ln_kernel<<<Bz * Sz, blk>>>(x2, tmp, ln3g, ln3b, out);
}

// round 6
// speedup vs baseline: 7.1245x; 4.4140x over previous
#include <cuda_runtime.h>
#include <cuda_fp16.h>
#include <cstdint>

#define Bz  2
#define Sz  1024
#define Dz  2048
#define Hz  16
#define DHz 128
#define DFFz 8192
#define NX   (Bz*Sz*Dz)
#define NQ   (Bz*Hz*Sz*DHz)
#define NSC  33554432
#define NFF  (Bz*Sz*DFFz)
#define NW_H (Hz*Dz*DHz)
#define NW_P (Dz*Dz)
#define NW_F (Dz*DFFz)

typedef __half half_t;

// ---------------- scratch (device globals; no allocation allowed) ----------
__device__ __align__(16) float g_sc[NSC];
__device__ __align__(16) float g_t[NX], g_r1[NX], g_r2[NX];
__device__ __align__(16) half_t g_xh[NX], g_eh[NX], g_1h[NX], g_2h[NX];
__device__ __align__(16) half_t g_qh[NQ], g_kh[NQ], g_vh[NQ];  // v is transposed [z][DH][S]
__device__ __align__(16) half_t g_ah[NSC];
__device__ __align__(16) half_t g_ch[NX];
__device__ __align__(16) half_t g_fh[NFF];
__device__ __align__(16) half_t g_w1h[3*NW_H], g_w2h[3*NW_H];  // per-head W^T [h][DH][D]
__device__ __align__(16) half_t g_ph[2*NW_P];                  // wp1^T, wp2^T [D][D]
__device__ __align__(16) half_t g_Fh[2*NW_F];                  // wff1^T [DFF][D], wff2^T [D][DFF]

// ---------------- PTX helpers ----------------
__device__ __forceinline__ uint32_t s2u(const void* p){
    uint32_t a; asm("{ .reg .u64 t; cvta.to.shared.u64 t,%1; cvt.u32.u64 %0,t; }":"=r"(a):"l"(p)); return a;
}
__device__ __forceinline__ void cpa(uint32_t d,const void* s){
    asm volatile("cp.async.cg.shared.global [%0], [%1], 16;"::"r"(d),"l"(s));
}
#define CP_COMMIT() asm volatile("cp.async.commit_group;":::"memory")
__device__ __forceinline__ void cp_w0(){ asm volatile("cp.async.wait_group 0;":::"memory"); }
__device__ __forceinline__ void cp_w1(){ asm volatile("cp.async.wait_group 1;":::"memory"); }

__device__ __forceinline__ void ldm4(uint32_t* r, uint32_t addr){
    asm volatile("ldmatrix.sync.aligned.m8n8.x4.shared.b16 {%0,%1,%2,%3}, [%4];"
        : "=r"(r[0]),"=r"(r[1]),"=r"(r[2]),"=r"(r[3]) : "r"(addr));
}
__device__ __forceinline__ void mma16816(float* c, const uint32_t* a, const uint32_t* b){
    asm volatile("mma.sync.aligned.m16n8k16.row.col.f32.f16.f16.f32 "
        "{%0,%1,%2,%3}, {%4,%5,%6,%7}, {%8,%9}, {%0,%1,%2,%3};"
        : "+f"(c[0]),"+f"(c[1]),"+f"(c[2]),"+f"(c[3])
        : "r"(a[0]),"r"(a[1]),"r"(a[2]),"r"(a[3]), "r"(b[0]),"r"(b[1]));
}

// fill 128-row x 32-half tile into smem rows of 80B stride (40 halves)
__device__ __forceinline__ void fill_t(uint32_t dst, const half_t* g, int ld, int k0, int tid){
#pragma unroll
    for(int i=0;i<2;i++){
        int c = tid + i*256;
        int r = c>>2, ch = c&3;
        cpa(dst + r*80 + ch*16, (const char*)(g + (size_t)r*ld + k0) + ch*16);
    }
}

// ---------------- core mma.sync GEMM: C[128x128] = A[M,K] * B[N,K]^T ------
// 256 threads, 8 warps as 2(m) x 4(n), warp tile 64x32.
// EPI: 0=fp32 C; 1=fp16 C; 2=fp16 transposed C[n][m]
template<int EPI,bool RELU,bool BIAS>
__device__ __forceinline__ void mm(
    const half_t* __restrict__ A,int lda,
    const half_t* __restrict__ B,int ldb,
    const float* __restrict__ bias,float alpha,
    float* __restrict__ C, half_t* __restrict__ Ch, long ldc,
    int K,int m0,int n0)
{
    __shared__ __align__(16) char smem[40960];   // 2 stages x (A 10240 + B 10240)
    uint32_t sb = s2u(smem);
    const int tid = threadIdx.x, lane = tid & 31, wid = tid >> 5;
    const int wm = wid & 1, wn = wid >> 1;

    A += (size_t)m0 * lda;
    B += (size_t)n0 * ldb;

    float acc[4][4][4];
#pragma unroll
    for(int i=0;i<4;i++)
#pragma unroll
        for(int j=0;j<4;j++)
#pragma unroll
            for(int q=0;q<4;q++) acc[i][j][q]=0.f;

    const int num = K >> 5;
    fill_t(sb,       A, lda, 0, tid);
    fill_t(sb+10240, B, ldb, 0, tid);
    CP_COMMIT();

    const uint32_t a_base = (uint32_t)((wm*64 + (lane&15))*80 + (lane>>4)*16);
    const uint32_t b_base = (uint32_t)((wn*32 + (lane&7) + ((lane>>4)<<3))*80 + ((lane>>3)&1)*16);

    for(int c=0;c<num;c++){
        uint32_t st = sb + (uint32_t)(c&1)*20480;
        if(c+1<num){
            uint32_t bb = sb + (uint32_t)((c+1)&1)*20480;
            int k1 = (c+1) << 5;
            fill_t(bb,       A, lda, k1, tid);
            fill_t(bb+10240, B, ldb, k1, tid);
            CP_COMMIT();
            cp_w1();
        } else cp_w0();
        __syncthreads();

        uint32_t aoff = st + a_base;
        uint32_t boff = st + 10240 + b_base;
#pragma unroll
        for(int ks=0;ks<2;ks++){
            uint32_t af[4][4], bf[4][2], bt[4];
#pragma unroll
            for(int mf=0;mf<4;mf++) ldm4(af[mf], aoff + mf*1280 + ks*32);
            ldm4(bt, boff + ks*32);
            bf[0][0]=bt[0]; bf[0][1]=bt[1]; bf[1][0]=bt[2]; bf[1][1]=bt[3];
            ldm4(bt, boff + 1280 + ks*32);
            bf[2][0]=bt[0]; bf[2][1]=bt[1]; bf[3][0]=bt[2]; bf[3][1]=bt[3];
#pragma unroll
            for(int mf=0;mf<4;mf++)
#pragma unroll
                for(int nf=0;nf<4;nf++) mma16816(acc[mf][nf], af[mf], bf[nf]);
        }
        __syncthreads();
    }

    // epilogue
#pragma unroll
    for(int mf=0;mf<4;mf++){
#pragma unroll
        for(int nf=0;nf<4;nf++){
            int r  = m0 + wm*64 + mf*16 + (lane>>2);
            int cc = n0 + wn*32 + nf*8  + (lane&3)*2;
            float v0=acc[mf][nf][0]*alpha, v1=acc[mf][nf][1]*alpha;
            float v2=acc[mf][nf][2]*alpha, v3=acc[mf][nf][3]*alpha;
            if(BIAS){ float b0=bias[cc], b1=bias[cc+1]; v0+=b0; v1+=b1; v2+=b0; v3+=b1; }
            if(RELU){ v0=fmaxf(v0,0.f); v1=fmaxf(v1,0.f); v2=fmaxf(v2,0.f); v3=fmaxf(v3,0.f); }
            if(EPI==0){
                *(float2*)(C + (size_t)r*ldc + cc)     = make_float2(v0,v1);
                *(float2*)(C + (size_t)(r+8)*ldc + cc) = make_float2(v2,v3);
            } else if(EPI==1){
                *(__half2*)(Ch + (size_t)r*ldc + cc)     = __floats2half2_rn(v0,v1);
                *(__half2*)(Ch + (size_t)(r+8)*ldc + cc) = __floats2half2_rn(v2,v3);
            } else {
                Ch[(size_t)cc*ldc + r]       = __float2half_rn(v0);
                Ch[(size_t)(cc+1)*ldc + r]   = __float2half_rn(v1);
                Ch[(size_t)cc*ldc + r+8]     = __float2half_rn(v2);
                Ch[(size_t)(cc+1)*ldc + r+8] = __float2half_rn(v3);
            }
        }
    }
}

// ---------------- GEMM wrapper kernels ----------------
__global__ void __launch_bounds__(256)
k_proj(const half_t* x,const half_t* w,const float* bias,half_t* o){
    int z=blockIdx.z,b=z>>4,h=z&15;
    mm<1,false,true>(x+(size_t)b*Sz*Dz,Dz, w+(size_t)h*DHz*Dz,Dz,
        bias+h*DHz,1.0f, nullptr,o+(size_t)z*Sz*DHz,DHz, Dz, blockIdx.x*128,0);
}
__global__ void __launch_bounds__(256)
k_projv(const half_t* x,const half_t* w,const float* bias,half_t* o){
    int z=blockIdx.z,b=z>>4,h=z&15;
    mm<2,false,true>(x+(size_t)b*Sz*Dz,Dz, w+(size_t)h*DHz*Dz,Dz,
        bias+h*DHz,1.0f, nullptr,o+(size_t)z*DHz*Sz,Sz, Dz, blockIdx.x*128,0);
}
__global__ void __launch_bounds__(256)
k_scores(const half_t* q,const half_t* k,float* sc){
    size_t z=blockIdx.z;
    mm<0,false,false>(q+z*Sz*DHz,DHz, k+z*Sz*DHz,DHz,
        nullptr,0.08838834764831845f, sc+z*Sz*Sz,nullptr,Sz, DHz,
        blockIdx.x*128, blockIdx.y*128);
}
__global__ void __launch_bounds__(256)
k_attnv(const half_t* a,const half_t* v,half_t* cat){
    size_t z=blockIdx.z; int b=blockIdx.z>>4,h=blockIdx.z&15;
    mm<1,false,false>(a+z*Sz*Sz,Sz, v+z*DHz*Sz,Sz,
        nullptr,1.0f, nullptr,cat+(size_t)b*Sz*Dz+h*DHz,Dz, Sz, blockIdx.x*128,0);
}
__global__ void __launch_bounds__(256)
k_lin32(const half_t* a,int lda,const half_t* b,int ldb,
        const float* bias,float* C,int ldc,int K){
    mm<0,false,true>(a,lda,b,ldb,bias,1.0f,C,nullptr,ldc,K,
        blockIdx.x*128, blockIdx.y*128);
}
__global__ void __launch_bounds__(256)
k_linrelu(const half_t* a,int lda,const half_t* b,int ldb,
          const float* bias,half_t* Ch,int ldc,int K){
    mm<1,true,true>(a,lda,b,ldb,bias,1.0f,nullptr,Ch,ldc,K,
        blockIdx.x*128, blockIdx.y*128);
}

// ---------------- conversions / softmax / layernorm ----------------
__global__ void __launch_bounds__(256)
k_h(const float4* __restrict__ in, __half2* __restrict__ o, int n4){
    int i=blockIdx.x*256+threadIdx.x; if(i>=n4) return;
    float4 v=in[i];
    o[2*i]   = __floats2half2_rn(v.x,v.y);
    o[2*i+1] = __floats2half2_rn(v.z,v.w);
}
// [z][R][C] fp32 -> [z][C][R] fp16
__global__ void k_th(const float* __restrict__ in, half_t* __restrict__ o, int R, int C){
    __shared__ float t[32][33];
    size_t zb=(size_t)blockIdx.z*R*C;
    int c0=blockIdx.x*32, r0=blockIdx.y*32, x=threadIdx.x, y=threadIdx.y;
#pragma unroll
    for(int i=0;i<32;i+=8) t[y+i][x]=in[zb+(size_t)(r0+y+i)*C+c0+x];
    __syncthreads();
#pragma unroll
    for(int i=0;i<32;i+=8)
        o[zb+(size_t)(c0+y+i)*R+r0+x]=__float2half_rn(t[x][y+i]);
}
// softmax over QUERY axis (columns of each SxS matrix), fp16 out
__global__ void __launch_bounds__(256)
k_softmax(const float* __restrict__ sc, half_t* __restrict__ o){
    size_t base=(size_t)blockIdx.y*Sz*Sz;
    int kcol=blockIdx.x*256+threadIdx.x;
    const float* p=sc+base+kcol;
    float mx=-1e30f;
    for(int q=0;q<Sz;q++) mx=fmaxf(mx,p[(size_t)q*Sz]);
    float sum=0.f;
    for(int q=0;q<Sz;q++) sum+=__expf(p[(size_t)q*Sz]-mx);
    float inv=1.0f/sum;
    for(int q=0;q<Sz;q++)
        o[base+(size_t)q*Sz+kcol]=__float2half_rn(__expf(p[(size_t)q*Sz]-mx)*inv);
}
__global__ void __launch_bounds__(256)
k_addln(const float* __restrict__ xa,const float* __restrict__ xb,
        const float* __restrict__ gg,const float* __restrict__ bb,
        float* __restrict__ out, half_t* __restrict__ oh){
    int row=blockIdx.x;
    const float* xr=xa+(size_t)row*Dz;
    const float* yr=xb+(size_t)row*Dz;
    float v[8]; float s=0.f,s2=0.f;
#pragma unroll
    for(int i=0;i<8;i++){ int c=threadIdx.x+i*256; v[i]=xr[c]+yr[c]; s+=v[i]; s2+=v[i]*v[i]; }
    __shared__ float rs[8],rs2[8];
#pragma unroll
    for(int o=16;o>0;o>>=1){ s+=__shfl_xor_sync(0xffffffffu,s,o); s2+=__shfl_xor_sync(0xffffffffu,s2,o); }
    int wid=threadIdx.x>>5,lid=threadIdx.x&31;
    if(lid==0){ rs[wid]=s; rs2[wid]=s2; }
    __syncthreads();
    if(threadIdx.x<32){
        s=(threadIdx.x<8)?rs[threadIdx.x]:0.f; s2=(threadIdx.x<8)?rs2[threadIdx.x]:0.f;
#pragma unroll
        for(int o=4;o>0;o>>=1){ s+=__shfl_xor_sync(0xffffffffu,s,o); s2+=__shfl_xor_sync(0xffffffffu,s2,o); }
        if(threadIdx.x==0){ rs[0]=s; rs2[0]=s2; }
    }
    __syncthreads();
    float mean=rs[0]*(1.0f/Dz);
    float var=rs2[0]*(1.0f/Dz)-mean*mean;
    float inv=rsqrtf(var+1e-5f);
#pragma unroll
    for(int i=0;i<8;i++){
        int c=threadIdx.x+i*256;
        float o=(v[i]-mean)*inv*gg[c]+bb[c];
        out[(size_t)row*Dz+c]=o;
        if(oh) oh[(size_t)row*Dz+c]=__float2half_rn(o);
    }
}

// ---------------- launch ----------------
#define GA(v,s) do{ void* _p; cudaGetSymbolAddress(&_p,s); v=(decltype(v))_p; }while(0)

extern "C" void kernel_launch(void* const* d_in,const int* in_sizes,int n_in,
                              void* d_out,int out_size)
{
    const float* x   =(const float*)d_in[0];
    const float* enc =(const float*)d_in[1];
    const float* wq1 =(const float*)d_in[2];
    const float* wk1 =(const float*)d_in[3];
    const float* wv1 =(const float*)d_in[4];
    const float* bq1 =(const float*)d_in[5];
    const float* bk1 =(const float*)d_in[6];
    const float* bv1 =(const float*)d_in[7];
    const float* wp1 =(const float*)d_in[8];
    const float* bp1 =(const float*)d_in[9];
    const float* wq2 =(const float*)d_in[10];
    const float* wk2 =(const float*)d_in[11];
    const float* wv2 =(const float*)d_in[12];
    const float* bq2 =(const float*)d_in[13];
    const float* bk2 =(const float*)d_in[14];
    const float* bv2 =(const float*)d_in[15];
    const float* wp2 =(const float*)d_in[16];
    const float* bp2 =(const float*)d_in[17];
    const float* ln1g=(const float*)d_in[18];
    const float* ln1b=(const float*)d_in[19];
    const float* ln2g=(const float*)d_in[20];
    const float* ln2b=(const float*)d_in[21];
    const float* ln3g=(const float*)d_in[22];
    const float* ln3b=(const float*)d_in[23];
    const float* wff1=(const float*)d_in[24];
    const float* bff1=(const float*)d_in[25];
    const float* wff2=(const float*)d_in[26];
    const float* bff2=(const float*)d_in[27];
    float* out=(float*)d_out;

    float *sc,*tp,*r1,*r2;
    half_t *xh,*eh,*h1,*h2,*qh,*kh,*vh,*ah,*ch,*fh,*w1,*w2,*ph,*Fh;
    GA(sc,g_sc); GA(tp,g_t); GA(r1,g_r1); GA(r2,g_r2);
    GA(xh,g_xh); GA(eh,g_eh); GA(h1,g_1h); GA(h2,g_2h);
    GA(qh,g_qh); GA(kh,g_kh); GA(vh,g_vh); GA(ah,g_ah);
    GA(ch,g_ch); GA(fh,g_fh);
    GA(w1,g_w1h); GA(w2,g_w2h); GA(ph,g_ph); GA(Fh,g_Fh);

    dim3 tb(32,8);
    // weight transposes (to [out][in]) + fp16 conversion
    k_th<<<dim3(DHz/32,Dz/32,Hz),tb>>>(wq1,w1,Dz,DHz);
    k_th<<<dim3(DHz/32,Dz/32,Hz),tb>>>(wk1,w1+NW_H,Dz,DHz);
    k_th<<<dim3(DHz/32,Dz/32,Hz),tb>>>(wv1,w1+2*NW_H,Dz,DHz);
    k_th<<<dim3(DHz/32,Dz/32,Hz),tb>>>(wq2,w2,Dz,DHz);
    k_th<<<dim3(DHz/32,Dz/32,Hz),tb>>>(wk2,w2+NW_H,Dz,DHz);
    k_th<<<dim3(DHz/32,Dz/32,Hz),tb>>>(wv2,w2+2*NW_H,Dz,DHz);
    k_th<<<dim3(Dz/32,Dz/32,1),tb>>>(wp1,ph,Dz,Dz);
    k_th<<<dim3(Dz/32,Dz/32,1),tb>>>(wp2,ph+NW_P,Dz,Dz);
    k_th<<<dim3(DFFz/32,Dz/32,1),tb>>>(wff1,Fh,Dz,DFFz);
    k_th<<<dim3(Dz/32,DFFz/32,1),tb>>>(wff2,Fh+NW_F,DFFz,Dz);
    k_h<<<NX/4/256,256>>>((const float4*)x,(__half2*)xh,NX/4);
    k_h<<<NX/4/256,256>>>((const float4*)enc,(__half2*)eh,NX/4);

    dim3 gp(Sz/128,1,Bz*Hz), gs(Sz/128,Sz/128,Bz*Hz), gm(Sz/256,Bz*Hz);
    dim3 gpp(2*Sz/128,Dz/128), gf1(2*Sz/128,DFFz/128);

    // ---- self attention ----
    k_proj <<<gp,256>>>(xh,w1,bq1,qh);
    k_proj <<<gp,256>>>(xh,w1+NW_H,bk1,kh);
    k_projv<<<gp,256>>>(xh,w1+2*NW_H,bv1,vh);
    k_scores<<<gs,256>>>(qh,kh,sc);
    k_softmax<<<gm,256>>>(sc,ah);
    k_attnv<<<gp,256>>>(ah,vh,ch);
    k_lin32<<<gpp,256>>>(ch,Dz,ph,Dz,bp1,tp,Dz,Dz);
    k_addln<<<Bz*Sz,256>>>(x,tp,ln1g,ln1b,r1,h1);

    // ---- cross attention: q from encoder_output, k/v from x1 ----
    k_proj <<<gp,256>>>(eh,w2,bq2,qh);
    k_proj <<<gp,256>>>(h1,w2+NW_H,bk2,kh);
    k_projv<<<gp,256>>>(h1,w2+2*NW_H,bv2,vh);
    k_scores<<<gs,256>>>(qh,kh,sc);
    k_softmax<<<gm,256>>>(sc,ah);
    k_attnv<<<gp,256>>>(ah,vh,ch);
    k_lin32<<<gpp,256>>>(ch,Dz,ph+NW_P,Dz,bp2,tp,Dz,Dz);
    k_addln<<<Bz*Sz,256>>>(r1,tp,ln2g,ln2b,r2,h2);

    // ---- feed forward ----
    k_linrelu<<<gf1,256>>>(h2,Dz,Fh,Dz,bff1,fh,DFFz,Dz);
    k_lin32<<<gpp,256>>>(fh,DFFz,Fh+NW_F,DFFz,bff2,tp,Dz,DFFz);
    k_addln<<<Bz*Sz,256>>>(r2,tp,ln3g,ln3b,out,nullptr);
}

// round 9
// speedup vs baseline: 7.5743x; 1.0631x over previous
#include <cuda_runtime.h>
#include <cuda_fp16.h>
#include <cstdint>

#define Bz  2
#define Sz  1024
#define Dz  2048
#define Hz  16
#define DHz 128
#define DFFz 8192
#define NX   (Bz*Sz*Dz)
#define NQ   (Bz*Hz*Sz*DHz)
#define NSC  33554432
#define NFF  (Bz*Sz*DFFz)
#define NW_H (Hz*Dz*DHz)
#define NW_P (Dz*Dz)
#define NW_F (Dz*DFFz)

typedef __half half_t;

// ---------------- scratch (device globals; no allocation allowed) ----------
__device__ __align__(16) float g_sc[NSC];
__device__ __align__(16) float g_t[NX], g_r1[NX], g_r2[NX];
__device__ __align__(16) half_t g_xh[NX], g_eh[NX], g_1h[NX], g_2h[NX];
__device__ __align__(16) half_t g_qh[NQ], g_kh[NQ], g_vh[NQ];  // v natural [z][S][DH]
__device__ __align__(16) half_t g_ah[NSC];
__device__ __align__(16) half_t g_ch[NX];
__device__ __align__(16) half_t g_fh[NFF];
__device__ __align__(16) half_t g_w1c[3*NW_H], g_w2c[3*NW_H];  // natural [H][D][DH]
__device__ __align__(16) half_t g_pc[2*NW_P];                  // wp1,wp2 natural [D][D]
__device__ __align__(16) half_t g_Fc[2*NW_F];                  // wff1 [D][DFF], wff2 [DFF][D]

// ---------------- PTX helpers ----------------
__device__ __forceinline__ uint32_t s2u(const void* p){
    uint32_t a; asm("{ .reg .u64 t; cvta.to.shared.u64 t,%1; cvt.u32.u64 %0,t; }":"=r"(a):"l"(p)); return a;
}
__device__ __forceinline__ void cpa(uint32_t d,const void* s){
    asm volatile("cp.async.cg.shared.global [%0], [%1], 16;"::"r"(d),"l"(s));
}
#define CP_COMMIT() asm volatile("cp.async.commit_group;":::"memory")
__device__ __forceinline__ void cp_w0(){ asm volatile("cp.async.wait_group 0;":::"memory"); }
__device__ __forceinline__ void cp_w1(){ asm volatile("cp.async.wait_group 1;":::"memory"); }

__device__ __forceinline__ void ldm4(uint32_t* r, uint32_t addr){
    asm volatile("ldmatrix.sync.aligned.m8n8.x4.shared.b16 {%0,%1,%2,%3}, [%4];"
        : "=r"(r[0]),"=r"(r[1]),"=r"(r[2]),"=r"(r[3]) : "r"(addr));
}
__device__ __forceinline__ void ldm4t(uint32_t* r, uint32_t addr){
    asm volatile("ldmatrix.sync.aligned.m8n8.x4.trans.shared.b16 {%0,%1,%2,%3}, [%4];"
        : "=r"(r[0]),"=r"(r[1]),"=r"(r[2]),"=r"(r[3]) : "r"(addr));
}
__device__ __forceinline__ void mma16816(float* c, const uint32_t* a, const uint32_t* b){
    asm volatile("mma.sync.aligned.m16n8k16.row.col.f32.f16.f16.f32 "
        "{%0,%1,%2,%3}, {%4,%5,%6,%7}, {%8,%9}, {%0,%1,%2,%3};"
        : "+f"(c[0]),"+f"(c[1]),"+f"(c[2]),"+f"(c[3])
        : "r"(a[0]),"r"(a[1]),"r"(a[2]),"r"(a[3]), "r"(b[0]),"r"(b[1]));
}

// A-style tile: 128 rows x 32 halves, 80B row stride
__device__ __forceinline__ void fill_a(uint32_t dst, const half_t* g, int ld, int k0, int tid){
#pragma unroll
    for(int i=0;i<2;i++){
        int c = tid + i*256;
        int r = c>>2, ch = c&3;
        cpa(dst + r*80 + ch*16, (const char*)(g + (size_t)r*ld + k0) + ch*16);
    }
}
// TRB tile: 32 k-rows x 128 halves, 272B row stride; g pre-offset by n0
__device__ __forceinline__ void fill_bt(uint32_t dst, const half_t* g, int ld, int k0, int tid){
#pragma unroll
    for(int i=0;i<2;i++){
        int c = tid + i*256;
        int r = c>>4, ch = c&15;
        cpa(dst + r*272 + ch*16, (const char*)(g + (size_t)(k0+r)*ld) + ch*16);
    }
}

// ---------------- core mma.sync GEMM: C[128x128] tile ----------------------
// A row-major [M,K]; B: TRB? [K,N] natural (ldb = N row stride) : [N,K] (ldb = K row stride).
// 256 threads, 8 warps 2(m) x 4(n), warp tile 64x32.
// EPI: 0=fp32 C; 1=fp16 C
template<int EPI,bool RELU,bool BIAS,bool TRB>
__device__ __forceinline__ void mm(
    const half_t* __restrict__ A,int lda,
    const half_t* __restrict__ B,int ldb,
    const float* __restrict__ bias,float alpha,
    float* __restrict__ C, half_t* __restrict__ Ch, long ldc,
    int K,int m0,int n0)
{
    extern __shared__ __align__(16) char smem[];   // 3 stages x 20480
    uint32_t sb = s2u(smem);
    const int tid = threadIdx.x, lane = tid & 31, wid = tid >> 5;
    const int wm = wid & 1, wn = wid >> 1;

    A += (size_t)m0 * lda;
    B += TRB ? (size_t)n0 : (size_t)n0 * ldb;

    float acc[4][4][4];
#pragma unroll
    for(int i=0;i<4;i++)
#pragma unroll
        for(int j=0;j<4;j++)
#pragma unroll
            for(int q=0;q<4;q++) acc[i][j][q]=0.f;

    const int num = K >> 5;
    // prologue: stages 0,1
    fill_a(sb, A, lda, 0, tid);
    if(TRB) fill_bt(sb+10240, B, ldb, 0, tid);
    else    fill_a (sb+10240, B, ldb, 0, tid);
    CP_COMMIT();
    if(num>1){
        fill_a(sb+20480, A, lda, 32, tid);
        if(TRB) fill_bt(sb+30720, B, ldb, 32, tid);
        else    fill_a (sb+30720, B, ldb, 32, tid);
    }
    CP_COMMIT();

    const uint32_t a_base = (uint32_t)((wm*64 + (lane&15))*80 + (lane>>4)*16);
    // non-trans B addressing ([N,K] rows)
    const uint32_t b_base  = (uint32_t)((wn*32 + (lane&7) + ((lane>>4)<<3))*80 + ((lane>>3)&1)*16);
    // trans B addressing ([K,N] rows): k row and n col per lane group
    const uint32_t bt_row  = (uint32_t)(((lane>>3)&1)*8 + (lane&7));
    const uint32_t bt_col  = (uint32_t)(wn*32 + ((lane>>4)<<3));

    for(int c=0;c<num;c++){
        if(c+1<num) cp_w1(); else cp_w0();
        __syncthreads();
        if(c+2<num){
            uint32_t nb = sb + (uint32_t)((c+2)%3)*20480;
            int k1 = (c+2) << 5;
            fill_a(nb, A, lda, k1, tid);
            if(TRB) fill_bt(nb+10240, B, ldb, k1, tid);
            else    fill_a (nb+10240, B, ldb, k1, tid);
        }
        CP_COMMIT();

        uint32_t st = sb + (uint32_t)(c%3)*20480;
        uint32_t aoff = st + a_base;
#pragma unroll
        for(int ks=0;ks<2;ks++){
            uint32_t af[4][4], bf[4][2], bt[4];
#pragma unroll
            for(int mf=0;mf<4;mf++) ldm4(af[mf], aoff + mf*1280 + ks*32);
            if(TRB){
                uint32_t bo = st + 10240 + (ks*16 + bt_row)*272 + bt_col*2;
                ldm4t(bt, bo);
                bf[0][0]=bt[0]; bf[0][1]=bt[1]; bf[1][0]=bt[2]; bf[1][1]=bt[3];
                ldm4t(bt, bo + 32);   // +16 n-cols
                bf[2][0]=bt[0]; bf[2][1]=bt[1]; bf[3][0]=bt[2]; bf[3][1]=bt[3];
            } else {
                uint32_t bo = st + 10240 + b_base;
                ldm4(bt, bo + ks*32);
                bf[0][0]=bt[0]; bf[0][1]=bt[1]; bf[1][0]=bt[2]; bf[1][1]=bt[3];
                ldm4(bt, bo + 1280 + ks*32);
                bf[2][0]=bt[0]; bf[2][1]=bt[1]; bf[3][0]=bt[2]; bf[3][1]=bt[3];
            }
#pragma unroll
            for(int mf=0;mf<4;mf++)
#pragma unroll
                for(int nf=0;nf<4;nf++) mma16816(acc[mf][nf], af[mf], bf[nf]);
        }
        __syncthreads();
    }

    // epilogue
#pragma unroll
    for(int mf=0;mf<4;mf++){
#pragma unroll
        for(int nf=0;nf<4;nf++){
            int r  = m0 + wm*64 + mf*16 + (lane>>2);
            int cc = n0 + wn*32 + nf*8  + (lane&3)*2;
            float v0=acc[mf][nf][0]*alpha, v1=acc[mf][nf][1]*alpha;
            float v2=acc[mf][nf][2]*alpha, v3=acc[mf][nf][3]*alpha;
            if(BIAS){ float b0=bias[cc], b1=bias[cc+1]; v0+=b0; v1+=b1; v2+=b0; v3+=b1; }
            if(RELU){ v0=fmaxf(v0,0.f); v1=fmaxf(v1,0.f); v2=fmaxf(v2,0.f); v3=fmaxf(v3,0.f); }
            if(EPI==0){
                *(float2*)(C + (size_t)r*ldc + cc)     = make_float2(v0,v1);
                *(float2*)(C + (size_t)(r+8)*ldc + cc) = make_float2(v2,v3);
            } else {
                *(__half2*)(Ch + (size_t)r*ldc + cc)     = __floats2half2_rn(v0,v1);
                *(__half2*)(Ch + (size_t)(r+8)*ldc + cc) = __floats2half2_rn(v2,v3);
            }
        }
    }
}

#define SMB (3*20480)

// ---------------- GEMM wrapper kernels ----------------
__global__ void __launch_bounds__(256)
k_proj(const half_t* x,const half_t* w,const float* bias,half_t* o){
    int z=blockIdx.z,b=z>>4,h=z&15;
    mm<1,false,true,true>(x+(size_t)b*Sz*Dz,Dz, w+(size_t)h*Dz*DHz,DHz,
        bias+h*DHz,1.0f, nullptr,o+(size_t)z*Sz*DHz,DHz, Dz, blockIdx.x*128,0);
}
__global__ void __launch_bounds__(256)
k_scores(const half_t* q,const half_t* k,float* sc){
    size_t z=blockIdx.z;
    mm<0,false,false,false>(q+z*Sz*DHz,DHz, k+z*Sz*DHz,DHz,
        nullptr,0.08838834764831845f, sc+z*Sz*Sz,nullptr,Sz, DHz,
        blockIdx.x*128, blockIdx.y*128);
}
__global__ void __launch_bounds__(256)
k_attnv(const half_t* a,const half_t* v,half_t* cat){
    size_t z=blockIdx.z; int b=blockIdx.z>>4,h=blockIdx.z&15;
    mm<1,false,false,true>(a+z*Sz*Sz,Sz, v+z*Sz*DHz,DHz,
        nullptr,1.0f, nullptr,cat+(size_t)b*Sz*Dz+h*DHz,Dz, Sz, blockIdx.x*128,0);
}
__global__ void __launch_bounds__(256)
k_lin32(const half_t* a,int lda,const half_t* b,int ldb,
        const float* bias,float* C,int ldc,int K){
    mm<0,false,true,true>(a,lda,b,ldb,bias,1.0f,C,nullptr,ldc,K,
        blockIdx.x*128, blockIdx.y*128);
}
__global__ void __launch_bounds__(256)
k_linrelu(const half_t* a,int lda,const half_t* b,int ldb,
          const float* bias,half_t* Ch,int ldc,int K){
    mm<1,true,true,true>(a,lda,b,ldb,bias,1.0f,nullptr,Ch,ldc,K,
        blockIdx.x*128, blockIdx.y*128);
}

// ---------------- conversions / softmax / layernorm ----------------
__global__ void __launch_bounds__(256)
k_h(const float4* __restrict__ in, __half2* __restrict__ o, int n4){
    int i=blockIdx.x*256+threadIdx.x; if(i>=n4) return;
    float4 v=in[i];
    o[2*i]   = __floats2half2_rn(v.x,v.y);
    o[2*i+1] = __floats2half2_rn(v.z,v.w);
}
// softmax over QUERY axis (columns of each SxS matrix), fp16 out; 2-pass online
__global__ void __launch_bounds__(256)
k_softmax(const float* __restrict__ sc, half_t* __restrict__ o){
    size_t base=(size_t)blockIdx.y*Sz*Sz;
    int kcol=blockIdx.x*256+threadIdx.x;
    const float* p=sc+base+kcol;
    float mx=-1e30f, s=0.f;
#pragma unroll 8
    for(int q=0;q<Sz;q++){
        float v=p[(size_t)q*Sz];
        float nm=fmaxf(mx,v);
        s = s*__expf(mx-nm) + __expf(v-nm);
        mx=nm;
    }
    float inv=1.0f/s;
#pragma unroll 8
    for(int q=0;q<Sz;q++)
        o[base+(size_t)q*Sz+kcol]=__float2half_rn(__expf(p[(size_t)q*Sz]-mx)*inv);
}
__global__ void __launch_bounds__(256)
k_addln(const float* __restrict__ xa,const float* __restrict__ xb,
        const float* __restrict__ gg,const float* __restrict__ bb,
        float* __restrict__ out, half_t* __restrict__ oh){
    int row=blockIdx.x;
    const float* xr=xa+(size_t)row*Dz;
    const float* yr=xb+(size_t)row*Dz;
    float v[8]; float s=0.f,s2=0.f;
#pragma unroll
    for(int i=0;i<8;i++){ int c=threadIdx.x+i*256; v[i]=xr[c]+yr[c]; s+=v[i]; s2+=v[i]*v[i]; }
    __shared__ float rs[8],rs2[8];
#pragma unroll
    for(int o=16;o>0;o>>=1){ s+=__shfl_xor_sync(0xffffffffu,s,o); s2+=__shfl_xor_sync(0xffffffffu,s2,o); }
    int wid=threadIdx.x>>5,lid=threadIdx.x&31;
    if(lid==0){ rs[wid]=s; rs2[wid]=s2; }
    __syncthreads();
    if(threadIdx.x<32){
        s=(threadIdx.x<8)?rs[threadIdx.x]:0.f; s2=(threadIdx.x<8)?rs2[threadIdx.x]:0.f;
#pragma unroll
        for(int o=4;o>0;o>>=1){ s+=__shfl_xor_sync(0xffffffffu,s,o); s2+=__shfl_xor_sync(0xffffffffu,s2,o); }
        if(threadIdx.x==0){ rs[0]=s; rs2[0]=s2; }
    }
    __syncthreads();
    float mean=rs[0]*(1.0f/Dz);
    float var=rs2[0]*(1.0f/Dz)-mean*mean;
    float inv=rsqrtf(var+1e-5f);
#pragma unroll
    for(int i=0;i<8;i++){
        int c=threadIdx.x+i*256;
        float o=(v[i]-mean)*inv*gg[c]+bb[c];
        out[(size_t)row*Dz+c]=o;
        if(oh) oh[(size_t)row*Dz+c]=__float2half_rn(o);
    }
}

// ---------------- launch ----------------
#define GA(v,s) do{ void* _p; cudaGetSymbolAddress(&_p,s); v=(decltype(v))_p; }while(0)

extern "C" void kernel_launch(void* const* d_in,const int* in_sizes,int n_in,
                              void* d_out,int out_size)
{
    const float* x   =(const float*)d_in[0];
    const float* enc =(const float*)d_in[1];
    const float* wq1 =(const float*)d_in[2];
    const float* wk1 =(const float*)d_in[3];
    const float* wv1 =(const float*)d_in[4];
    const float* bq1 =(const float*)d_in[5];
    const float* bk1 =(const float*)d_in[6];
    const float* bv1 =(const float*)d_in[7];
    const float* wp1 =(const float*)d_in[8];
    const float* bp1 =(const float*)d_in[9];
    const float* wq2 =(const float*)d_in[10];
    const float* wk2 =(const float*)d_in[11];
    const float* wv2 =(const float*)d_in[12];
    const float* bq2 =(const float*)d_in[13];
    const float* bk2 =(const float*)d_in[14];
    const float* bv2 =(const float*)d_in[15];
    const float* wp2 =(const float*)d_in[16];
    const float* bp2 =(const float*)d_in[17];
    const float* ln1g=(const float*)d_in[18];
    const float* ln1b=(const float*)d_in[19];
    const float* ln2g=(const float*)d_in[20];
    const float* ln2b=(const float*)d_in[21];
    const float* ln3g=(const float*)d_in[22];
    const float* ln3b=(const float*)d_in[23];
    const float* wff1=(const float*)d_in[24];
    const float* bff1=(const float*)d_in[25];
    const float* wff2=(const float*)d_in[26];
    const float* bff2=(const float*)d_in[27];
    float* out=(float*)d_out;

    float *sc,*tp,*r1,*r2;
    half_t *xh,*eh,*h1,*h2,*qh,*kh,*vh,*ah,*ch,*fh,*w1,*w2,*pc,*Fc;
    GA(sc,g_sc); GA(tp,g_t); GA(r1,g_r1); GA(r2,g_r2);
    GA(xh,g_xh); GA(eh,g_eh); GA(h1,g_1h); GA(h2,g_2h);
    GA(qh,g_qh); GA(kh,g_kh); GA(vh,g_vh); GA(ah,g_ah);
    GA(ch,g_ch); GA(fh,g_fh);
    GA(w1,g_w1c); GA(w2,g_w2c); GA(pc,g_pc); GA(Fc,g_Fc);

    cudaFuncSetAttribute(k_proj,   cudaFuncAttributeMaxDynamicSharedMemorySize,SMB);
    cudaFuncSetAttribute(k_scores, cudaFuncAttributeMaxDynamicSharedMemorySize,SMB);
    cudaFuncSetAttribute(k_attnv,  cudaFuncAttributeMaxDynamicSharedMemorySize,SMB);
    cudaFuncSetAttribute(k_lin32,  cudaFuncAttributeMaxDynamicSharedMemorySize,SMB);
    cudaFuncSetAttribute(k_linrelu,cudaFuncAttributeMaxDynamicSharedMemorySize,SMB);

    // pure casts (coalesced) — no transposes
    k_h<<<NW_H/4/256,256>>>((const float4*)wq1,(__half2*)w1,NW_H/4);
    k_h<<<NW_H/4/256,256>>>((const float4*)wk1,(__half2*)(w1+NW_H),NW_H/4);
    k_h<<<NW_H/4/256,256>>>((const float4*)wv1,(__half2*)(w1+2*NW_H),NW_H/4);
    k_h<<<NW_H/4/256,256>>>((const float4*)wq2,(__half2*)w2,NW_H/4);
    k_h<<<NW_H/4/256,256>>>((const float4*)wk2,(__half2*)(w2+NW_H),NW_H/4);
    k_h<<<NW_H/4/256,256>>>((const float4*)wv2,(__half2*)(w2+2*NW_H),NW_H/4);
    k_h<<<NW_P/4/256,256>>>((const float4*)wp1,(__half2*)pc,NW_P/4);
    k_h<<<NW_P/4/256,256>>>((const float4*)wp2,(__half2*)(pc+NW_P),NW_P/4);
    k_h<<<NW_F/4/256,256>>>((const float4*)wff1,(__half2*)Fc,NW_F/4);
    k_h<<<NW_F/4/256,256>>>((const float4*)wff2,(__half2*)(Fc+NW_F),NW_F/4);
    k_h<<<NX/4/256,256>>>((const float4*)x,(__half2*)xh,NX/4);
    k_h<<<NX/4/256,256>>>((const float4*)enc,(__half2*)eh,NX/4);

    dim3 gp(Sz/128,1,Bz*Hz), gs(Sz/128,Sz/128,Bz*Hz), gm(Sz/256,Bz*Hz);
    dim3 gpp(2*Sz/128,Dz/128), gf1(2*Sz/128,DFFz/128);

    // ---- self attention ----
    k_proj <<<gp,256,SMB>>>(xh,w1,bq1,qh);
    k_proj <<<gp,256,SMB>>>(xh,w1+NW_H,bk1,kh);
    k_proj <<<gp,256,SMB>>>(xh,w1+2*NW_H,bv1,vh);
    k_scores<<<gs,256,SMB>>>(qh,kh,sc);
    k_softmax<<<gm,256>>>(sc,ah);
    k_attnv<<<gp,256,SMB>>>(ah,vh,ch);
    k_lin32<<<gpp,256,SMB>>>(ch,Dz,pc,Dz,bp1,tp,Dz,Dz);
    k_addln<<<Bz*Sz,256>>>(x,tp,ln1g,ln1b,r1,h1);

    // ---- cross attention: q from encoder_output, k/v from x1 ----
    k_proj <<<gp,256,SMB>>>(eh,w2,bq2,qh);
    k_proj <<<gp,256,SMB>>>(h1,w2+NW_H,bk2,kh);
    k_proj <<<gp,256,SMB>>>(h1,w2+2*NW_H,bv2,vh);
    k_scores<<<gs,256,SMB>>>(qh,kh,sc);
    k_softmax<<<gm,256>>>(sc,ah);
    k_attnv<<<gp,256,SMB>>>(ah,vh,ch);
    k_lin32<<<gpp,256,SMB>>>(ch,Dz,pc+NW_P,Dz,bp2,tp,Dz,Dz);
    k_addln<<<Bz*Sz,256>>>(r1,tp,ln2g,ln2b,r2,h2);

    // ---- feed forward (ldb = natural row stride of B: wff1->DFFz, wff2->Dz) ----
    k_linrelu<<<gf1,256,SMB>>>(h2,Dz,Fc,DFFz,bff1,fh,DFFz,Dz);
    k_lin32<<<gpp,256,SMB>>>(fh,DFFz,Fc+NW_F,Dz,bff2,tp,Dz,DFFz);
    k_addln<<<Bz*Sz,256>>>(r2,tp,ln3g,ln3b,out,nullptr);
}

// round 10
// speedup vs baseline: 8.5764x; 1.1323x over previous
#include <cuda_runtime.h>
#include <cuda_fp16.h>
#include <cstdint>

#define Bz  2
#define Sz  1024
#define Dz  2048
#define Hz  16
#define DHz 128
#define DFFz 8192
#define NX   (Bz*Sz*Dz)
#define NQ   (Bz*Hz*Sz*DHz)
#define NSC  33554432
#define NFF  (Bz*Sz*DFFz)
#define NW_H (Hz*Dz*DHz)
#define NW_P (Dz*Dz)
#define NW_F (Dz*DFFz)

typedef __half half_t;

// ---------------- scratch (device globals; no allocation allowed) ----------
__device__ __align__(16) float g_sc[NSC];
__device__ __align__(16) float g_t[NX], g_r1[NX], g_r2[NX];
__device__ __align__(16) float2 g_part[32*8*Sz];               // softmax partial (max,sum)
__device__ __align__(16) half_t g_xh[NX], g_eh[NX], g_1h[NX], g_2h[NX];
__device__ __align__(16) half_t g_qh[NQ], g_kh[NQ], g_vh[NQ];  // v natural [z][S][DH]
__device__ __align__(16) half_t g_ah[NSC];
__device__ __align__(16) half_t g_ch[NX];
__device__ __align__(16) half_t g_fh[NFF];
__device__ __align__(16) half_t g_w1c[3*NW_H], g_w2c[3*NW_H];  // natural [H][D][DH]
__device__ __align__(16) half_t g_pc[2*NW_P];                  // wp1,wp2 natural [D][D]
__device__ __align__(16) half_t g_Fc[2*NW_F];                  // wff1 [D][DFF], wff2 [DFF][D]

// ---------------- PTX helpers ----------------
__device__ __forceinline__ uint32_t s2u(const void* p){
    uint32_t a; asm("{ .reg .u64 t; cvta.to.shared.u64 t,%1; cvt.u32.u64 %0,t; }":"=r"(a):"l"(p)); return a;
}
__device__ __forceinline__ void cpa(uint32_t d,const void* s){
    asm volatile("cp.async.cg.shared.global [%0], [%1], 16;"::"r"(d),"l"(s));
}
#define CP_COMMIT() asm volatile("cp.async.commit_group;":::"memory")
__device__ __forceinline__ void cp_w0(){ asm volatile("cp.async.wait_group 0;":::"memory"); }
__device__ __forceinline__ void cp_w1(){ asm volatile("cp.async.wait_group 1;":::"memory"); }

__device__ __forceinline__ void ldm4(uint32_t* r, uint32_t addr){
    asm volatile("ldmatrix.sync.aligned.m8n8.x4.shared.b16 {%0,%1,%2,%3}, [%4];"
        : "=r"(r[0]),"=r"(r[1]),"=r"(r[2]),"=r"(r[3]) : "r"(addr));
}
__device__ __forceinline__ void ldm4t(uint32_t* r, uint32_t addr){
    asm volatile("ldmatrix.sync.aligned.m8n8.x4.trans.shared.b16 {%0,%1,%2,%3}, [%4];"
        : "=r"(r[0]),"=r"(r[1]),"=r"(r[2]),"=r"(r[3]) : "r"(addr));
}
__device__ __forceinline__ void mma16816(float* c, const uint32_t* a, const uint32_t* b){
    asm volatile("mma.sync.aligned.m16n8k16.row.col.f32.f16.f16.f32 "
        "{%0,%1,%2,%3}, {%4,%5,%6,%7}, {%8,%9}, {%0,%1,%2,%3};"
        : "+f"(c[0]),"+f"(c[1]),"+f"(c[2]),"+f"(c[3])
        : "r"(a[0]),"r"(a[1]),"r"(a[2]),"r"(a[3]), "r"(b[0]),"r"(b[1]));
}

// A-style tile: 128 rows x 32 halves, 80B row stride
__device__ __forceinline__ void fill_a(uint32_t dst, const half_t* g, int ld, int k0, int tid){
#pragma unroll
    for(int i=0;i<2;i++){
        int c = tid + i*256;
        int r = c>>2, ch = c&3;
        cpa(dst + r*80 + ch*16, (const char*)(g + (size_t)r*ld + k0) + ch*16);
    }
}
// TRB tile: 32 k-rows x 128 halves, 272B row stride; g pre-offset by n0
__device__ __forceinline__ void fill_bt(uint32_t dst, const half_t* g, int ld, int k0, int tid){
#pragma unroll
    for(int i=0;i<2;i++){
        int c = tid + i*256;
        int r = c>>4, ch = c&15;
        cpa(dst + r*272 + ch*16, (const char*)(g + (size_t)(k0+r)*ld) + ch*16);
    }
}

// ---------------- core mma.sync GEMM: C[128x128] tile ----------------------
// A row-major [M,K]; B: TRB? [K,N] natural (ldb = N row stride) : [N,K] (ldb = K row stride).
// 256 threads, 8 warps 2(m) x 4(n), warp tile 64x32.
// EPI: 0=fp32 C; 1=fp16 C
template<int EPI,bool RELU,bool BIAS,bool TRB>
__device__ __forceinline__ void mm(
    const half_t* __restrict__ A,int lda,
    const half_t* __restrict__ B,int ldb,
    const float* __restrict__ bias,float alpha,
    float* __restrict__ C, half_t* __restrict__ Ch, long ldc,
    int K,int m0,int n0)
{
    extern __shared__ __align__(16) char smem[];   // 3 stages x 20480
    uint32_t sb = s2u(smem);
    const int tid = threadIdx.x, lane = tid & 31, wid = tid >> 5;
    const int wm = wid & 1, wn = wid >> 1;

    A += (size_t)m0 * lda;
    B += TRB ? (size_t)n0 : (size_t)n0 * ldb;

    float acc[4][4][4];
#pragma unroll
    for(int i=0;i<4;i++)
#pragma unroll
        for(int j=0;j<4;j++)
#pragma unroll
            for(int q=0;q<4;q++) acc[i][j][q]=0.f;

    const int num = K >> 5;
    // prologue: stages 0,1
    fill_a(sb, A, lda, 0, tid);
    if(TRB) fill_bt(sb+10240, B, ldb, 0, tid);
    else    fill_a (sb+10240, B, ldb, 0, tid);
    CP_COMMIT();
    if(num>1){
        fill_a(sb+20480, A, lda, 32, tid);
        if(TRB) fill_bt(sb+30720, B, ldb, 32, tid);
        else    fill_a (sb+30720, B, ldb, 32, tid);
    }
    CP_COMMIT();

    const uint32_t a_base = (uint32_t)((wm*64 + (lane&15))*80 + (lane>>4)*16);
    const uint32_t b_base  = (uint32_t)((wn*32 + (lane&7) + ((lane>>4)<<3))*80 + ((lane>>3)&1)*16);
    const uint32_t bt_row  = (uint32_t)(((lane>>3)&1)*8 + (lane&7));
    const uint32_t bt_col  = (uint32_t)(wn*32 + ((lane>>4)<<3));

    for(int c=0;c<num;c++){
        if(c+1<num) cp_w1(); else cp_w0();
        __syncthreads();
        if(c+2<num){
            uint32_t nb = sb + (uint32_t)((c+2)%3)*20480;
            int k1 = (c+2) << 5;
            fill_a(nb, A, lda, k1, tid);
            if(TRB) fill_bt(nb+10240, B, ldb, k1, tid);
            else    fill_a (nb+10240, B, ldb, k1, tid);
        }
        CP_COMMIT();

        uint32_t st = sb + (uint32_t)(c%3)*20480;
        uint32_t aoff = st + a_base;
#pragma unroll
        for(int ks=0;ks<2;ks++){
            uint32_t af[4][4], bf[4][2], bt[4];
#pragma unroll
            for(int mf=0;mf<4;mf++) ldm4(af[mf], aoff + mf*1280 + ks*32);
            if(TRB){
                uint32_t bo = st + 10240 + (ks*16 + bt_row)*272 + bt_col*2;
                ldm4t(bt, bo);
                bf[0][0]=bt[0]; bf[0][1]=bt[1]; bf[1][0]=bt[2]; bf[1][1]=bt[3];
                ldm4t(bt, bo + 32);   // +16 n-cols
                bf[2][0]=bt[0]; bf[2][1]=bt[1]; bf[3][0]=bt[2]; bf[3][1]=bt[3];
            } else {
                uint32_t bo = st + 10240 + b_base;
                ldm4(bt, bo + ks*32);
                bf[0][0]=bt[0]; bf[0][1]=bt[1]; bf[1][0]=bt[2]; bf[1][1]=bt[3];
                ldm4(bt, bo + 1280 + ks*32);
                bf[2][0]=bt[0]; bf[2][1]=bt[1]; bf[3][0]=bt[2]; bf[3][1]=bt[3];
            }
#pragma unroll
            for(int mf=0;mf<4;mf++)
#pragma unroll
                for(int nf=0;nf<4;nf++) mma16816(acc[mf][nf], af[mf], bf[nf]);
        }
        // NOTE: no second __syncthreads — next iter's top barrier precedes
        // the only write to the stage being read here.
    }

    // epilogue
#pragma unroll
    for(int mf=0;mf<4;mf++){
#pragma unroll
        for(int nf=0;nf<4;nf++){
            int r  = m0 + wm*64 + mf*16 + (lane>>2);
            int cc = n0 + wn*32 + nf*8  + (lane&3)*2;
            float v0=acc[mf][nf][0]*alpha, v1=acc[mf][nf][1]*alpha;
            float v2=acc[mf][nf][2]*alpha, v3=acc[mf][nf][3]*alpha;
            if(BIAS){ float b0=bias[cc], b1=bias[cc+1]; v0+=b0; v1+=b1; v2+=b0; v3+=b1; }
            if(RELU){ v0=fmaxf(v0,0.f); v1=fmaxf(v1,0.f); v2=fmaxf(v2,0.f); v3=fmaxf(v3,0.f); }
            if(EPI==0){
                *(float2*)(C + (size_t)r*ldc + cc)     = make_float2(v0,v1);
                *(float2*)(C + (size_t)(r+8)*ldc + cc) = make_float2(v2,v3);
            } else {
                *(__half2*)(Ch + (size_t)r*ldc + cc)     = __floats2half2_rn(v0,v1);
                *(__half2*)(Ch + (size_t)(r+8)*ldc + cc) = __floats2half2_rn(v2,v3);
            }
        }
    }
}

#define SMB (3*20480)

// ---------------- GEMM wrapper kernels ----------------
// fused QKV projection: grid (8, 3, 32); y: 0=Q (input xq), 1=K, 2=V (input xkv)
__global__ void __launch_bounds__(256)
k_proj3(const half_t* xq,const half_t* xkv,const half_t* w,
        const float* bq,const float* bk,const float* bv,
        half_t* oq,half_t* ok,half_t* ov){
    int which=blockIdx.y;
    int z=blockIdx.z,b=z>>4,h=z&15;
    const half_t* A = (which==0)?xq:xkv;
    const float* bias = (which==0)?bq:((which==1)?bk:bv);
    half_t* o = (which==0)?oq:((which==1)?ok:ov);
    mm<1,false,true,true>(A+(size_t)b*Sz*Dz,Dz,
        w+(size_t)which*NW_H+(size_t)h*Dz*DHz,DHz,
        bias+h*DHz,1.0f, nullptr,o+(size_t)z*Sz*DHz,DHz, Dz, blockIdx.x*128,0);
}
__global__ void __launch_bounds__(256)
k_scores(const half_t* q,const half_t* k,float* sc){
    size_t z=blockIdx.z;
    mm<0,false,false,false>(q+z*Sz*DHz,DHz, k+z*Sz*DHz,DHz,
        nullptr,0.08838834764831845f, sc+z*Sz*Sz,nullptr,Sz, DHz,
        blockIdx.x*128, blockIdx.y*128);
}
__global__ void __launch_bounds__(256)
k_attnv(const half_t* a,const half_t* v,half_t* cat){
    size_t z=blockIdx.z; int b=blockIdx.z>>4,h=blockIdx.z&15;
    mm<1,false,false,true>(a+z*Sz*Sz,Sz, v+z*Sz*DHz,DHz,
        nullptr,1.0f, nullptr,cat+(size_t)b*Sz*Dz+h*DHz,Dz, Sz, blockIdx.x*128,0);
}
__global__ void __launch_bounds__(256)
k_lin32(const half_t* a,int lda,const half_t* b,int ldb,
        const float* bias,float* C,int ldc,int K){
    mm<0,false,true,true>(a,lda,b,ldb,bias,1.0f,C,nullptr,ldc,K,
        blockIdx.x*128, blockIdx.y*128);
}
__global__ void __launch_bounds__(256)
k_linrelu(const half_t* a,int lda,const half_t* b,int ldb,
          const float* bias,half_t* Ch,int ldc,int K){
    mm<1,true,true,true>(a,lda,b,ldb,bias,1.0f,nullptr,Ch,ldc,K,
        blockIdx.x*128, blockIdx.y*128);
}

// ---------------- conversions (single launch) ----------------
struct CvtArgs {
    const float4* in[12];
    __half2* out[12];
    int n4[12];
};
__global__ void __launch_bounds__(256)
k_hall(CvtArgs a){
    int seg = blockIdx.y;
    const float4* in = a.in[seg];
    __half2* o = a.out[seg];
    int n4 = a.n4[seg];
    for(int i=blockIdx.x*256+threadIdx.x; i<n4; i+=gridDim.x*256){
        float4 v=in[i];
        o[2*i]   = __floats2half2_rn(v.x,v.y);
        o[2*i+1] = __floats2half2_rn(v.z,v.w);
    }
}

// ---------------- softmax over QUERY axis: split stats + normalize ---------
// stats: grid (8, 32): block = 128-row chunk of one z; partial online (max,sum) per column
__global__ void __launch_bounds__(256)
k_smstat(const float* __restrict__ sc, float2* __restrict__ part){
    int z=blockIdx.y, rc=blockIdx.x;
    size_t base=(size_t)z*Sz*Sz + (size_t)rc*128*Sz;
#pragma unroll 1
    for(int c=threadIdx.x;c<Sz;c+=256){
        const float* p=sc+base+c;
        float m=-1e30f,s=0.f;
#pragma unroll 8
        for(int r=0;r<128;r++){
            float v=p[(size_t)r*Sz];
            float nm=fmaxf(m,v);
            s=s*__expf(m-nm)+__expf(v-nm);
            m=nm;
        }
        part[((size_t)z*8+rc)*Sz+c]=make_float2(m,s);
    }
}
// normalize: grid (8, 32): block = 128-row chunk; combines 8 partials, writes fp16 probs
__global__ void __launch_bounds__(256)
k_smnorm(const float* __restrict__ sc, const float2* __restrict__ part,
         half_t* __restrict__ o){
    __shared__ float sm[Sz], si[Sz];
    int z=blockIdx.y, rc=blockIdx.x;
    for(int c=threadIdx.x;c<Sz;c+=256){
        float m=-1e30f,s=0.f;
#pragma unroll
        for(int k=0;k<8;k++){
            float2 ps=part[((size_t)z*8+k)*Sz+c];
            float nm=fmaxf(m,ps.x);
            s=s*__expf(m-nm)+ps.y*__expf(ps.x-nm);
            m=nm;
        }
        sm[c]=m; si[c]=1.0f/s;
    }
    __syncthreads();
    size_t base=(size_t)z*Sz*Sz+(size_t)rc*128*Sz;
#pragma unroll 1
    for(int r=0;r<128;r++){
        size_t ro=base+(size_t)r*Sz;
#pragma unroll
        for(int j=0;j<4;j++){
            int c=threadIdx.x+j*256;
            o[ro+c]=__float2half_rn(__expf(sc[ro+c]-sm[c])*si[c]);
        }
    }
}

__global__ void __launch_bounds__(256)
k_addln(const float* __restrict__ xa,const float* __restrict__ xb,
        const float* __restrict__ gg,const float* __restrict__ bb,
        float* __restrict__ out, half_t* __restrict__ oh){
    int row=blockIdx.x;
    const float* xr=xa+(size_t)row*Dz;
    const float* yr=xb+(size_t)row*Dz;
    float v[8]; float s=0.f,s2=0.f;
#pragma unroll
    for(int i=0;i<8;i++){ int c=threadIdx.x+i*256; v[i]=xr[c]+yr[c]; s+=v[i]; s2+=v[i]*v[i]; }
    __shared__ float rs[8],rs2[8];
#pragma unroll
    for(int o=16;o>0;o>>=1){ s+=__shfl_xor_sync(0xffffffffu,s,o); s2+=__shfl_xor_sync(0xffffffffu,s2,o); }
    int wid=threadIdx.x>>5,lid=threadIdx.x&31;
    if(lid==0){ rs[wid]=s; rs2[wid]=s2; }
    __syncthreads();
    if(threadIdx.x<32){
        s=(threadIdx.x<8)?rs[threadIdx.x]:0.f; s2=(threadIdx.x<8)?rs2[threadIdx.x]:0.f;
#pragma unroll
        for(int o=4;o>0;o>>=1){ s+=__shfl_xor_sync(0xffffffffu,s,o); s2+=__shfl_xor_sync(0xffffffffu,s2,o); }
        if(threadIdx.x==0){ rs[0]=s; rs2[0]=s2; }
    }
    __syncthreads();
    float mean=rs[0]*(1.0f/Dz);
    float var=rs2[0]*(1.0f/Dz)-mean*mean;
    float inv=rsqrtf(var+1e-5f);
#pragma unroll
    for(int i=0;i<8;i++){
        int c=threadIdx.x+i*256;
        float o=(v[i]-mean)*inv*gg[c]+bb[c];
        out[(size_t)row*Dz+c]=o;
        if(oh) oh[(size_t)row*Dz+c]=__float2half_rn(o);
    }
}

// ---------------- launch ----------------
#define GA(v,s) do{ void* _p; cudaGetSymbolAddress(&_p,s); v=(decltype(v))_p; }while(0)

extern "C" void kernel_launch(void* const* d_in,const int* in_sizes,int n_in,
                              void* d_out,int out_size)
{
    const float* x   =(const float*)d_in[0];
    const float* enc =(const float*)d_in[1];
    const float* wq1 =(const float*)d_in[2];
    const float* wk1 =(const float*)d_in[3];
    const float* wv1 =(const float*)d_in[4];
    const float* bq1 =(const float*)d_in[5];
    const float* bk1 =(const float*)d_in[6];
    const float* bv1 =(const float*)d_in[7];
    const float* wp1 =(const float*)d_in[8];
    const float* bp1 =(const float*)d_in[9];
    const float* wq2 =(const float*)d_in[10];
    const float* wk2 =(const float*)d_in[11];
    const float* wv2 =(const float*)d_in[12];
    const float* bq2 =(const float*)d_in[13];
    const float* bk2 =(const float*)d_in[14];
    const float* bv2 =(const float*)d_in[15];
    const float* wp2 =(const float*)d_in[16];
    const float* bp2 =(const float*)d_in[17];
    const float* ln1g=(const float*)d_in[18];
    const float* ln1b=(const float*)d_in[19];
    const float* ln2g=(const float*)d_in[20];
    const float* ln2b=(const float*)d_in[21];
    const float* ln3g=(const float*)d_in[22];
    const float* ln3b=(const float*)d_in[23];
    const float* wff1=(const float*)d_in[24];
    const float* bff1=(const float*)d_in[25];
    const float* wff2=(const float*)d_in[26];
    const float* bff2=(const float*)d_in[27];
    float* out=(float*)d_out;

    float *sc,*tp,*r1,*r2; float2* part;
    half_t *xh,*eh,*h1,*h2,*qh,*kh,*vh,*ah,*ch,*fh,*w1,*w2,*pc,*Fc;
    GA(sc,g_sc); GA(tp,g_t); GA(r1,g_r1); GA(r2,g_r2); GA(part,g_part);
    GA(xh,g_xh); GA(eh,g_eh); GA(h1,g_1h); GA(h2,g_2h);
    GA(qh,g_qh); GA(kh,g_kh); GA(vh,g_vh); GA(ah,g_ah);
    GA(ch,g_ch); GA(fh,g_fh);
    GA(w1,g_w1c); GA(w2,g_w2c); GA(pc,g_pc); GA(Fc,g_Fc);

    cudaFuncSetAttribute(k_proj3,  cudaFuncAttributeMaxDynamicSharedMemorySize,SMB);
    cudaFuncSetAttribute(k_scores, cudaFuncAttributeMaxDynamicSharedMemorySize,SMB);
    cudaFuncSetAttribute(k_attnv,  cudaFuncAttributeMaxDynamicSharedMemorySize,SMB);
    cudaFuncSetAttribute(k_lin32,  cudaFuncAttributeMaxDynamicSharedMemorySize,SMB);
    cudaFuncSetAttribute(k_linrelu,cudaFuncAttributeMaxDynamicSharedMemorySize,SMB);

    // all fp32->fp16 casts in ONE launch
    CvtArgs ca;
    ca.in[0]=(const float4*)wq1;  ca.out[0]=(__half2*)w1;           ca.n4[0]=NW_H/4;
    ca.in[1]=(const float4*)wk1;  ca.out[1]=(__half2*)(w1+NW_H);    ca.n4[1]=NW_H/4;
    ca.in[2]=(const float4*)wv1;  ca.out[2]=(__half2*)(w1+2*NW_H);  ca.n4[2]=NW_H/4;
    ca.in[3]=(const float4*)wq2;  ca.out[3]=(__half2*)w2;           ca.n4[3]=NW_H/4;
    ca.in[4]=(const float4*)wk2;  ca.out[4]=(__half2*)(w2+NW_H);    ca.n4[4]=NW_H/4;
    ca.in[5]=(const float4*)wv2;  ca.out[5]=(__half2*)(w2+2*NW_H);  ca.n4[5]=NW_H/4;
    ca.in[6]=(const float4*)wp1;  ca.out[6]=(__half2*)pc;           ca.n4[6]=NW_P/4;
    ca.in[7]=(const float4*)wp2;  ca.out[7]=(__half2*)(pc+NW_P);    ca.n4[7]=NW_P/4;
    ca.in[8]=(const float4*)wff1; ca.out[8]=(__half2*)Fc;           ca.n4[8]=NW_F/4;
    ca.in[9]=(const float4*)wff2; ca.out[9]=(__half2*)(Fc+NW_F);    ca.n4[9]=NW_F/4;
    ca.in[10]=(const float4*)x;   ca.out[10]=(__half2*)xh;          ca.n4[10]=NX/4;
    ca.in[11]=(const float4*)enc; ca.out[11]=(__half2*)eh;          ca.n4[11]=NX/4;
    k_hall<<<dim3(512,12),256>>>(ca);

    dim3 gp3(Sz/128,3,Bz*Hz), gp(Sz/128,1,Bz*Hz), gs(Sz/128,Sz/128,Bz*Hz);
    dim3 gsm(8,Bz*Hz);
    dim3 gpp(2*Sz/128,Dz/128), gf1(2*Sz/128,DFFz/128);

    // ---- self attention ----
    k_proj3<<<gp3,256,SMB>>>(xh,xh,w1,bq1,bk1,bv1,qh,kh,vh);
    k_scores<<<gs,256,SMB>>>(qh,kh,sc);
    k_smstat<<<gsm,256>>>(sc,part);
    k_smnorm<<<gsm,256>>>(sc,part,ah);
    k_attnv<<<gp,256,SMB>>>(ah,vh,ch);
    k_lin32<<<gpp,256,SMB>>>(ch,Dz,pc,Dz,bp1,tp,Dz,Dz);
    k_addln<<<Bz*Sz,256>>>(x,tp,ln1g,ln1b,r1,h1);

    // ---- cross attention: q from encoder_output, k/v from x1 ----
    k_proj3<<<gp3,256,SMB>>>(eh,h1,w2,bq2,bk2,bv2,qh,kh,vh);
    k_scores<<<gs,256,SMB>>>(qh,kh,sc);
    k_smstat<<<gsm,256>>>(sc,part);
    k_smnorm<<<gsm,256>>>(sc,part,ah);
    k_attnv<<<gp,256,SMB>>>(ah,vh,ch);
    k_lin32<<<gpp,256,SMB>>>(ch,Dz,pc+NW_P,Dz,bp2,tp,Dz,Dz);
    k_addln<<<Bz*Sz,256>>>(r1,tp,ln2g,ln2b,r2,h2);

    // ---- feed forward (ldb = natural row stride of B: wff1->DFFz, wff2->Dz) ----
    k_linrelu<<<gf1,256,SMB>>>(h2,Dz,Fc,DFFz,bff1,fh,DFFz,Dz);
    k_lin32<<<gpp,256,SMB>>>(fh,DFFz,Fc+NW_F,Dz,bff2,tp,Dz,DFFz);
    k_addln<<<Bz*Sz,256>>>(r2,tp,ln3g,ln3b,out,nullptr);
}

// round 11
// speedup vs baseline: 9.0550x; 1.0558x over previous
#include <cuda_runtime.h>
#include <cuda_fp16.h>
#include <cstdint>

#define Bz  2
#define Sz  1024
#define Dz  2048
#define Hz  16
#define DHz 128
#define DFFz 8192
#define NX   (Bz*Sz*Dz)
#define NQ   (Bz*Hz*Sz*DHz)
#define NSC  33554432
#define NFF  (Bz*Sz*DFFz)
#define NW_H (Hz*Dz*DHz)
#define NW_P (Dz*Dz)
#define NW_F (Dz*DFFz)

typedef __half half_t;

// ---------------- scratch (device globals; no allocation allowed) ----------
__device__ __align__(16) float g_sc[NSC];
__device__ __align__(16) float g_t[NX], g_r1[NX], g_r2[NX];
__device__ __align__(16) float2 g_part[32*8*Sz];               // softmax partial (max,sum)
__device__ __align__(16) half_t g_xh[NX], g_eh[NX], g_1h[NX], g_2h[NX];
__device__ __align__(16) half_t g_qh[NQ], g_kh[NQ], g_vh[NQ];  // v natural [z][S][DH]
__device__ __align__(16) half_t g_ah[NSC];
__device__ __align__(16) half_t g_ch[NX];
__device__ __align__(16) half_t g_fh[NFF];
__device__ __align__(16) half_t g_w1c[3*NW_H], g_w2c[3*NW_H];  // natural [H][D][DH]
__device__ __align__(16) half_t g_pc[2*NW_P];                  // wp1,wp2 natural [D][D]
__device__ __align__(16) half_t g_Fc[2*NW_F];                  // wff1 [D][DFF], wff2 [DFF][D]

// ---------------- PTX helpers ----------------
__device__ __forceinline__ uint32_t s2u(const void* p){
    uint32_t a; asm("{ .reg .u64 t; cvta.to.shared.u64 t,%1; cvt.u32.u64 %0,t; }":"=r"(a):"l"(p)); return a;
}
__device__ __forceinline__ void cpa(uint32_t d,const void* s){
    asm volatile("cp.async.cg.shared.global [%0], [%1], 16;"::"r"(d),"l"(s));
}
#define CP_COMMIT() asm volatile("cp.async.commit_group;":::"memory")
__device__ __forceinline__ void cp_w0(){ asm volatile("cp.async.wait_group 0;":::"memory"); }
__device__ __forceinline__ void cp_w1(){ asm volatile("cp.async.wait_group 1;":::"memory"); }

__device__ __forceinline__ void ldm4(uint32_t* r, uint32_t addr){
    asm volatile("ldmatrix.sync.aligned.m8n8.x4.shared.b16 {%0,%1,%2,%3}, [%4];"
        : "=r"(r[0]),"=r"(r[1]),"=r"(r[2]),"=r"(r[3]) : "r"(addr));
}
__device__ __forceinline__ void ldm4t(uint32_t* r, uint32_t addr){
    asm volatile("ldmatrix.sync.aligned.m8n8.x4.trans.shared.b16 {%0,%1,%2,%3}, [%4];"
        : "=r"(r[0]),"=r"(r[1]),"=r"(r[2]),"=r"(r[3]) : "r"(addr));
}
__device__ __forceinline__ void mma16816(float* c, const uint32_t* a, const uint32_t* b){
    asm volatile("mma.sync.aligned.m16n8k16.row.col.f32.f16.f16.f32 "
        "{%0,%1,%2,%3}, {%4,%5,%6,%7}, {%8,%9}, {%0,%1,%2,%3};"
        : "+f"(c[0]),"+f"(c[1]),"+f"(c[2]),"+f"(c[3])
        : "r"(a[0]),"r"(a[1]),"r"(a[2]),"r"(a[3]), "r"(b[0]),"r"(b[1]));
}

// A-style tile: 128 rows x 32 halves, 80B row stride
__device__ __forceinline__ void fill_a(uint32_t dst, const half_t* g, int ld, int k0, int tid){
#pragma unroll
    for(int i=0;i<2;i++){
        int c = tid + i*256;
        int r = c>>2, ch = c&3;
        cpa(dst + r*80 + ch*16, (const char*)(g + (size_t)r*ld + k0) + ch*16);
    }
}
// TRB tile: 32 k-rows x 128 halves, 272B row stride; g pre-offset by n0
__device__ __forceinline__ void fill_bt(uint32_t dst, const half_t* g, int ld, int k0, int tid){
#pragma unroll
    for(int i=0;i<2;i++){
        int c = tid + i*256;
        int r = c>>4, ch = c&15;
        cpa(dst + r*272 + ch*16, (const char*)(g + (size_t)(k0+r)*ld) + ch*16);
    }
}

// ---------------- core mma.sync GEMM: C[128x128] tile ----------------------
// A row-major [M,K]; B: TRB? [K,N] natural (ldb = N row stride) : [N,K] (ldb = K row stride).
// 256 threads, 8 warps 2(m) x 4(n), warp tile 64x32.
// EPI: 0=fp32 C; 1=fp16 C.  STATS: also emit per-column online (max,sum) over
// this CTA's 128 rows into part[n0..n0+127] (softmax-over-rows partials).
template<int EPI,bool RELU,bool BIAS,bool TRB,bool STATS>
__device__ __forceinline__ void mm(
    const half_t* __restrict__ A,int lda,
    const half_t* __restrict__ B,int ldb,
    const float* __restrict__ bias,float alpha,
    float* __restrict__ C, half_t* __restrict__ Ch, long ldc,
    int K,int m0,int n0, float2* __restrict__ part)
{
    extern __shared__ __align__(16) char smem[];   // 3 stages x 20480
    uint32_t sb = s2u(smem);
    const int tid = threadIdx.x, lane = tid & 31, wid = tid >> 5;
    const int wm = wid & 1, wn = wid >> 1;

    A += (size_t)m0 * lda;
    B += TRB ? (size_t)n0 : (size_t)n0 * ldb;

    float acc[4][4][4];
#pragma unroll
    for(int i=0;i<4;i++)
#pragma unroll
        for(int j=0;j<4;j++)
#pragma unroll
            for(int q=0;q<4;q++) acc[i][j][q]=0.f;

    const int num = K >> 5;
    // prologue: stages 0,1
    fill_a(sb, A, lda, 0, tid);
    if(TRB) fill_bt(sb+10240, B, ldb, 0, tid);
    else    fill_a (sb+10240, B, ldb, 0, tid);
    CP_COMMIT();
    if(num>1){
        fill_a(sb+20480, A, lda, 32, tid);
        if(TRB) fill_bt(sb+30720, B, ldb, 32, tid);
        else    fill_a (sb+30720, B, ldb, 32, tid);
    }
    CP_COMMIT();

    const uint32_t a_base = (uint32_t)((wm*64 + (lane&15))*80 + (lane>>4)*16);
    const uint32_t b_base  = (uint32_t)((wn*32 + (lane&7) + ((lane>>4)<<3))*80 + ((lane>>3)&1)*16);
    const uint32_t bt_row  = (uint32_t)(((lane>>3)&1)*8 + (lane&7));
    const uint32_t bt_col  = (uint32_t)(wn*32 + ((lane>>4)<<3));

    for(int c=0;c<num;c++){
        if(c+1<num) cp_w1(); else cp_w0();
        __syncthreads();
        if(c+2<num){
            uint32_t nb = sb + (uint32_t)((c+2)%3)*20480;
            int k1 = (c+2) << 5;
            fill_a(nb, A, lda, k1, tid);
            if(TRB) fill_bt(nb+10240, B, ldb, k1, tid);
            else    fill_a (nb+10240, B, ldb, k1, tid);
        }
        CP_COMMIT();

        uint32_t st = sb + (uint32_t)(c%3)*20480;
        uint32_t aoff = st + a_base;
#pragma unroll
        for(int ks=0;ks<2;ks++){
            uint32_t af[4][4], bf[4][2], bt[4];
#pragma unroll
            for(int mf=0;mf<4;mf++) ldm4(af[mf], aoff + mf*1280 + ks*32);
            if(TRB){
                uint32_t bo = st + 10240 + (ks*16 + bt_row)*272 + bt_col*2;
                ldm4t(bt, bo);
                bf[0][0]=bt[0]; bf[0][1]=bt[1]; bf[1][0]=bt[2]; bf[1][1]=bt[3];
                ldm4t(bt, bo + 32);   // +16 n-cols
                bf[2][0]=bt[0]; bf[2][1]=bt[1]; bf[3][0]=bt[2]; bf[3][1]=bt[3];
            } else {
                uint32_t bo = st + 10240 + b_base;
                ldm4(bt, bo + ks*32);
                bf[0][0]=bt[0]; bf[0][1]=bt[1]; bf[1][0]=bt[2]; bf[1][1]=bt[3];
                ldm4(bt, bo + 1280 + ks*32);
                bf[2][0]=bt[0]; bf[2][1]=bt[1]; bf[3][0]=bt[2]; bf[3][1]=bt[3];
            }
#pragma unroll
            for(int mf=0;mf<4;mf++)
#pragma unroll
                for(int nf=0;nf<4;nf++) mma16816(acc[mf][nf], af[mf], bf[nf]);
        }
        // no second __syncthreads — next iter's top barrier precedes refill
    }

    // epilogue: write C
#pragma unroll
    for(int mf=0;mf<4;mf++){
#pragma unroll
        for(int nf=0;nf<4;nf++){
            int r  = m0 + wm*64 + mf*16 + (lane>>2);
            int cc = n0 + wn*32 + nf*8  + (lane&3)*2;
            float v0=acc[mf][nf][0]*alpha, v1=acc[mf][nf][1]*alpha;
            float v2=acc[mf][nf][2]*alpha, v3=acc[mf][nf][3]*alpha;
            if(BIAS){ float b0=bias[cc], b1=bias[cc+1]; v0+=b0; v1+=b1; v2+=b0; v3+=b1; }
            if(RELU){ v0=fmaxf(v0,0.f); v1=fmaxf(v1,0.f); v2=fmaxf(v2,0.f); v3=fmaxf(v3,0.f); }
            if(EPI==0){
                *(float2*)(C + (size_t)r*ldc + cc)     = make_float2(v0,v1);
                *(float2*)(C + (size_t)(r+8)*ldc + cc) = make_float2(v2,v3);
            } else {
                *(__half2*)(Ch + (size_t)r*ldc + cc)     = __floats2half2_rn(v0,v1);
                *(__half2*)(Ch + (size_t)(r+8)*ldc + cc) = __floats2half2_rn(v2,v3);
            }
        }
    }

    if(STATS){
        // column-wise online (max,sum) over this CTA's 128 rows.
        __syncthreads();                       // smem free after mainloop
        float2* st2 = (float2*)smem;           // [2][128]
        // thread-local over 8 rows per (nf, j) column
        float sm_[4][2], ss_[4][2];
#pragma unroll
        for(int nf=0;nf<4;nf++){
#pragma unroll
            for(int j=0;j<2;j++){
                float m=-1e30f,s=0.f;
#pragma unroll
                for(int mf=0;mf<4;mf++){
#pragma unroll
                    for(int h=0;h<2;h++){
                        float v=acc[mf][nf][j+2*h]*alpha;
                        float nm=fmaxf(m,v);
                        s=s*__expf(m-nm)+__expf(v-nm); m=nm;
                    }
                }
                sm_[nf][j]=m; ss_[nf][j]=s;
            }
        }
        // merge the 8 row-groups within the warp (lane bits 2..4), col in lane&3
#pragma unroll
        for(int nf=0;nf<4;nf++){
#pragma unroll
            for(int j=0;j<2;j++){
                float m=sm_[nf][j], s=ss_[nf][j];
#pragma unroll
                for(int o=4;o<=16;o<<=1){
                    float om=__shfl_xor_sync(0xffffffffu,m,o);
                    float os=__shfl_xor_sync(0xffffffffu,s,o);
                    float nm=fmaxf(m,om);
                    s=s*__expf(m-nm)+os*__expf(om-nm); m=nm;
                }
                if((lane>>2)==0)
                    st2[wm*128 + wn*32 + nf*8 + (lane&3)*2 + j]=make_float2(m,s);
            }
        }
        __syncthreads();
        if(tid<128){
            float2 a0=st2[tid], a1=st2[128+tid];
            float nm=fmaxf(a0.x,a1.x);
            float s=a0.y*__expf(a0.x-nm)+a1.y*__expf(a1.x-nm);
            part[n0+tid]=make_float2(nm,s);
        }
    }
}

#define SMB (3*20480)

// ---------------- GEMM wrapper kernels ----------------
// fused QKV projection: grid (8, 3, 32); y: 0=Q (input xq), 1=K, 2=V (input xkv)
__global__ void __launch_bounds__(256)
k_proj3(const half_t* xq,const half_t* xkv,const half_t* w,
        const float* bq,const float* bk,const float* bv,
        half_t* oq,half_t* ok,half_t* ov){
    int which=blockIdx.y;
    int z=blockIdx.z,b=z>>4,h=z&15;
    const half_t* A = (which==0)?xq:xkv;
    const float* bias = (which==0)?bq:((which==1)?bk:bv);
    half_t* o = (which==0)?oq:((which==1)?ok:ov);
    mm<1,false,true,true,false>(A+(size_t)b*Sz*Dz,Dz,
        w+(size_t)which*NW_H+(size_t)h*Dz*DHz,DHz,
        bias+h*DHz,1.0f, nullptr,o+(size_t)z*Sz*DHz,DHz, Dz, blockIdx.x*128,0, nullptr);
}
// scores + fused per-tile softmax stats
__global__ void __launch_bounds__(256)
k_scores(const half_t* q,const half_t* k,float* sc,float2* part){
    size_t z=blockIdx.z;
    mm<0,false,false,false,true>(q+z*Sz*DHz,DHz, k+z*Sz*DHz,DHz,
        nullptr,0.08838834764831845f, sc+z*Sz*Sz,nullptr,Sz, DHz,
        blockIdx.x*128, blockIdx.y*128,
        part + ((size_t)z*8 + blockIdx.x)*Sz);
}
__global__ void __launch_bounds__(256)
k_attnv(const half_t* a,const half_t* v,half_t* cat){
    size_t z=blockIdx.z; int b=blockIdx.z>>4,h=blockIdx.z&15;
    mm<1,false,false,true,false>(a+z*Sz*Sz,Sz, v+z*Sz*DHz,DHz,
        nullptr,1.0f, nullptr,cat+(size_t)b*Sz*Dz+h*DHz,Dz, Sz, blockIdx.x*128,0, nullptr);
}
__global__ void __launch_bounds__(256)
k_lin32(const half_t* a,int lda,const half_t* b,int ldb,
        const float* bias,float* C,int ldc,int K){
    mm<0,false,true,true,false>(a,lda,b,ldb,bias,1.0f,C,nullptr,ldc,K,
        blockIdx.x*128, blockIdx.y*128, nullptr);
}
__global__ void __launch_bounds__(256)
k_linrelu(const half_t* a,int lda,const half_t* b,int ldb,
          const float* bias,half_t* Ch,int ldc,int K){
    mm<1,true,true,true,false>(a,lda,b,ldb,bias,1.0f,nullptr,Ch,ldc,K,
        blockIdx.x*128, blockIdx.y*128, nullptr);
}

// ---------------- conversions (single launch) ----------------
struct CvtArgs {
    const float4* in[12];
    __half2* out[12];
    int n4[12];
};
__global__ void __launch_bounds__(256)
k_hall(CvtArgs a){
    int seg = blockIdx.y;
    const float4* in = a.in[seg];
    __half2* o = a.out[seg];
    int n4 = a.n4[seg];
    for(int i=blockIdx.x*256+threadIdx.x; i<n4; i+=gridDim.x*256){
        float4 v=in[i];
        o[2*i]   = __floats2half2_rn(v.x,v.y);
        o[2*i+1] = __floats2half2_rn(v.z,v.w);
    }
}

// ---------------- softmax normalize (stats now fused into k_scores) --------
// grid (8, 32): block = 128-row chunk; combines 8 partials, writes fp16 probs
__global__ void __launch_bounds__(256)
k_smnorm(const float* __restrict__ sc, const float2* __restrict__ part,
         half_t* __restrict__ o){
    __shared__ float sm[Sz], si[Sz];
    int z=blockIdx.y, rc=blockIdx.x;
    for(int c=threadIdx.x;c<Sz;c+=256){
        float m=-1e30f,s=0.f;
#pragma unroll
        for(int k=0;k<8;k++){
            float2 ps=part[((size_t)z*8+k)*Sz+c];
            float nm=fmaxf(m,ps.x);
            s=s*__expf(m-nm)+ps.y*__expf(ps.x-nm);
            m=nm;
        }
        sm[c]=m; si[c]=1.0f/s;
    }
    __syncthreads();
    size_t base=(size_t)z*Sz*Sz+(size_t)rc*128*Sz;
#pragma unroll 1
    for(int r=0;r<128;r++){
        size_t ro=base+(size_t)r*Sz;
#pragma unroll
        for(int j=0;j<4;j++){
            int c=threadIdx.x+j*256;
            o[ro+c]=__float2half_rn(__expf(sc[ro+c]-sm[c])*si[c]);
        }
    }
}

__global__ void __launch_bounds__(256)
k_addln(const float* __restrict__ xa,const float* __restrict__ xb,
        const float* __restrict__ gg,const float* __restrict__ bb,
        float* __restrict__ out, half_t* __restrict__ oh){
    int row=blockIdx.x;
    const float* xr=xa+(size_t)row*Dz;
    const float* yr=xb+(size_t)row*Dz;
    float v[8]; float s=0.f,s2=0.f;
#pragma unroll
    for(int i=0;i<8;i++){ int c=threadIdx.x+i*256; v[i]=xr[c]+yr[c]; s+=v[i]; s2+=v[i]*v[i]; }
    __shared__ float rs[8],rs2[8];
#pragma unroll
    for(int o=16;o>0;o>>=1){ s+=__shfl_xor_sync(0xffffffffu,s,o); s2+=__shfl_xor_sync(0xffffffffu,s2,o); }
    int wid=threadIdx.x>>5,lid=threadIdx.x&31;
    if(lid==0){ rs[wid]=s; rs2[wid]=s2; }
    __syncthreads();
    if(threadIdx.x<32){
        s=(threadIdx.x<8)?rs[threadIdx.x]:0.f; s2=(threadIdx.x<8)?rs2[threadIdx.x]:0.f;
#pragma unroll
        for(int o=4;o>0;o>>=1){ s+=__shfl_xor_sync(0xffffffffu,s,o); s2+=__shfl_xor_sync(0xffffffffu,s2,o); }
        if(threadIdx.x==0){ rs[0]=s; rs2[0]=s2; }
    }
    __syncthreads();
    float mean=rs[0]*(1.0f/Dz);
    float var=rs2[0]*(1.0f/Dz)-mean*mean;
    float inv=rsqrtf(var+1e-5f);
#pragma unroll
    for(int i=0;i<8;i++){
        int c=threadIdx.x+i*256;
        float o=(v[i]-mean)*inv*gg[c]+bb[c];
        out[(size_t)row*Dz+c]=o;
        if(oh) oh[(size_t)row*Dz+c]=__float2half_rn(o);
    }
}

// ---------------- launch ----------------
#define GA(v,s) do{ void* _p; cudaGetSymbolAddress(&_p,s); v=(decltype(v))_p; }while(0)

extern "C" void kernel_launch(void* const* d_in,const int* in_sizes,int n_in,
                              void* d_out,int out_size)
{
    const float* x   =(const float*)d_in[0];
    const float* enc =(const float*)d_in[1];
    const float* wq1 =(const float*)d_in[2];
    const float* wk1 =(const float*)d_in[3];
    const float* wv1 =(const float*)d_in[4];
    const float* bq1 =(const float*)d_in[5];
    const float* bk1 =(const float*)d_in[6];
    const float* bv1 =(const float*)d_in[7];
    const float* wp1 =(const float*)d_in[8];
    const float* bp1 =(const float*)d_in[9];
    const float* wq2 =(const float*)d_in[10];
    const float* wk2 =(const float*)d_in[11];
    const float* wv2 =(const float*)d_in[12];
    const float* bq2 =(const float*)d_in[13];
    const float* bk2 =(const float*)d_in[14];
    const float* bv2 =(const float*)d_in[15];
    const float* wp2 =(const float*)d_in[16];
    const float* bp2 =(const float*)d_in[17];
    const float* ln1g=(const float*)d_in[18];
    const float* ln1b=(const float*)d_in[19];
    const float* ln2g=(const float*)d_in[20];
    const float* ln2b=(const float*)d_in[21];
    const float* ln3g=(const float*)d_in[22];
    const float* ln3b=(const float*)d_in[23];
    const float* wff1=(const float*)d_in[24];
    const float* bff1=(const float*)d_in[25];
    const float* wff2=(const float*)d_in[26];
    const float* bff2=(const float*)d_in[27];
    float* out=(float*)d_out;

    float *sc,*tp,*r1,*r2; float2* part;
    half_t *xh,*eh,*h1,*h2,*qh,*kh,*vh,*ah,*ch,*fh,*w1,*w2,*pc,*Fc;
    GA(sc,g_sc); GA(tp,g_t); GA(r1,g_r1); GA(r2,g_r2); GA(part,g_part);
    GA(xh,g_xh); GA(eh,g_eh); GA(h1,g_1h); GA(h2,g_2h);
    GA(qh,g_qh); GA(kh,g_kh); GA(vh,g_vh); GA(ah,g_ah);
    GA(ch,g_ch); GA(fh,g_fh);
    GA(w1,g_w1c); GA(w2,g_w2c); GA(pc,g_pc); GA(Fc,g_Fc);

    cudaFuncSetAttribute(k_proj3,  cudaFuncAttributeMaxDynamicSharedMemorySize,SMB);
    cudaFuncSetAttribute(k_scores, cudaFuncAttributeMaxDynamicSharedMemorySize,SMB);
    cudaFuncSetAttribute(k_attnv,  cudaFuncAttributeMaxDynamicSharedMemorySize,SMB);
    cudaFuncSetAttribute(k_lin32,  cudaFuncAttributeMaxDynamicSharedMemorySize,SMB);
    cudaFuncSetAttribute(k_linrelu,cudaFuncAttributeMaxDynamicSharedMemorySize,SMB);

    // all fp32->fp16 casts in ONE launch
    CvtArgs ca;
    ca.in[0]=(const float4*)wq1;  ca.out[0]=(__half2*)w1;           ca.n4[0]=NW_H/4;
    ca.in[1]=(const float4*)wk1;  ca.out[1]=(__half2*)(w1+NW_H);    ca.n4[1]=NW_H/4;
    ca.in[2]=(const float4*)wv1;  ca.out[2]=(__half2*)(w1+2*NW_H);  ca.n4[2]=NW_H/4;
    ca.in[3]=(const float4*)wq2;  ca.out[3]=(__half2*)w2;           ca.n4[3]=NW_H/4;
    ca.in[4]=(const float4*)wk2;  ca.out[4]=(__half2*)(w2+NW_H);    ca.n4[4]=NW_H/4;
    ca.in[5]=(const float4*)wv2;  ca.out[5]=(__half2*)(w2+2*NW_H);  ca.n4[5]=NW_H/4;
    ca.in[6]=(const float4*)wp1;  ca.out[6]=(__half2*)pc;           ca.n4[6]=NW_P/4;
    ca.in[7]=(const float4*)wp2;  ca.out[7]=(__half2*)(pc+NW_P);    ca.n4[7]=NW_P/4;
    ca.in[8]=(const float4*)wff1; ca.out[8]=(__half2*)Fc;           ca.n4[8]=NW_F/4;
    ca.in[9]=(const float4*)wff2; ca.out[9]=(__half2*)(Fc+NW_F);    ca.n4[9]=NW_F/4;
    ca.in[10]=(const float4*)x;   ca.out[10]=(__half2*)xh;          ca.n4[10]=NX/4;
    ca.in[11]=(const float4*)enc; ca.out[11]=(__half2*)eh;          ca.n4[11]=NX/4;
    k_hall<<<dim3(512,12),256>>>(ca);

    dim3 gp3(Sz/128,3,Bz*Hz), gp(Sz/128,1,Bz*Hz), gs(Sz/128,Sz/128,Bz*Hz);
    dim3 gsm(8,Bz*Hz);
    dim3 gpp(2*Sz/128,Dz/128), gf1(2*Sz/128,DFFz/128);

    // ---- self attention ----
    k_proj3<<<gp3,256,SMB>>>(xh,xh,w1,bq1,bk1,bv1,qh,kh,vh);
    k_scores<<<gs,256,SMB>>>(qh,kh,sc,part);
    k_smnorm<<<gsm,256>>>(sc,part,ah);
    k_attnv<<<gp,256,SMB>>>(ah,vh,ch);
    k_lin32<<<gpp,256,SMB>>>(ch,Dz,pc,Dz,bp1,tp,Dz,Dz);
    k_addln<<<Bz*Sz,256>>>(x,tp,ln1g,ln1b,r1,h1);

    // ---- cross attention: q from encoder_output, k/v from x1 ----
    k_proj3<<<gp3,256,SMB>>>(eh,h1,w2,bq2,bk2,bv2,qh,kh,vh);
    k_scores<<<gs,256,SMB>>>(qh,kh,sc,part);
    k_smnorm<<<gsm,256>>>(sc,part,ah);
    k_attnv<<<gp,256,SMB>>>(ah,vh,ch);
    k_lin32<<<gpp,256,SMB>>>(ch,Dz,pc+NW_P,Dz,bp2,tp,Dz,Dz);
    k_addln<<<Bz*Sz,256>>>(r1,tp,ln2g,ln2b,r2,h2);

    // ---- feed forward (ldb = natural row stride of B: wff1->DFFz, wff2->Dz) ----
    k_linrelu<<<gf1,256,SMB>>>(h2,Dz,Fc,DFFz,bff1,fh,DFFz,Dz);
    k_lin32<<<gpp,256,SMB>>>(fh,DFFz,Fc+NW_F,Dz,bff2,tp,Dz,DFFz);
    k_addln<<<Bz*Sz,256>>>(r2,tp,ln3g,ln3b,out,nullptr);
}

// round 12
// speedup vs baseline: 9.7624x; 1.0781x over previous
#include <cuda_runtime.h>
#include <cuda_fp16.h>
#include <cstdint>

#define Bz  2
#define Sz  1024
#define Dz  2048
#define Hz  16
#define DHz 128
#define DFFz 8192
#define NX   (Bz*Sz*Dz)
#define NQ   (Bz*Hz*Sz*DHz)
#define NSC  33554432
#define NFF  (Bz*Sz*DFFz)
#define NW_H (Hz*Dz*DHz)
#define NW_P (Dz*Dz)
#define NW_F (Dz*DFFz)

typedef __half half_t;

// ---------------- scratch (device globals; no allocation allowed) ----------
__device__ __align__(16) float g_sc[NSC];
__device__ __align__(16) float g_t[NX], g_r1[NX], g_r2[NX];
__device__ __align__(16) float2 g_part[32*8*Sz];               // softmax partial (max,sum)
__device__ __align__(16) half_t g_xh[NX], g_eh[NX], g_1h[NX], g_2h[NX];
__device__ __align__(16) half_t g_qh[NQ], g_kh[NQ], g_vh[NQ];  // v natural [z][S][DH]
__device__ __align__(16) half_t g_ah[NSC];
__device__ __align__(16) half_t g_ch[NX];
__device__ __align__(16) half_t g_fh[NFF];
__device__ __align__(16) half_t g_w1c[3*NW_H], g_w2c[3*NW_H];  // natural [H][D][DH]
__device__ __align__(16) half_t g_pc[2*NW_P];                  // wp1,wp2 natural [D][D]
__device__ __align__(16) half_t g_Fc[2*NW_F];                  // wff1 [D][DFF], wff2 [DFF][D]

// ---------------- PTX helpers ----------------
__device__ __forceinline__ uint32_t s2u(const void* p){
    uint32_t a; asm("{ .reg .u64 t; cvta.to.shared.u64 t,%1; cvt.u32.u64 %0,t; }":"=r"(a):"l"(p)); return a;
}
__device__ __forceinline__ void cpa(uint32_t d,const void* s){
    asm volatile("cp.async.cg.shared.global [%0], [%1], 16;"::"r"(d),"l"(s));
}
#define CP_COMMIT() asm volatile("cp.async.commit_group;":::"memory")
__device__ __forceinline__ void cp_w0(){ asm volatile("cp.async.wait_group 0;":::"memory"); }
__device__ __forceinline__ void cp_w1(){ asm volatile("cp.async.wait_group 1;":::"memory"); }

__device__ __forceinline__ void ldm4(uint32_t* r, uint32_t addr){
    asm volatile("ldmatrix.sync.aligned.m8n8.x4.shared.b16 {%0,%1,%2,%3}, [%4];"
        : "=r"(r[0]),"=r"(r[1]),"=r"(r[2]),"=r"(r[3]) : "r"(addr));
}
__device__ __forceinline__ void ldm4t(uint32_t* r, uint32_t addr){
    asm volatile("ldmatrix.sync.aligned.m8n8.x4.trans.shared.b16 {%0,%1,%2,%3}, [%4];"
        : "=r"(r[0]),"=r"(r[1]),"=r"(r[2]),"=r"(r[3]) : "r"(addr));
}
__device__ __forceinline__ void mma16816(float* c, const uint32_t* a, const uint32_t* b){
    asm volatile("mma.sync.aligned.m16n8k16.row.col.f32.f16.f16.f32 "
        "{%0,%1,%2,%3}, {%4,%5,%6,%7}, {%8,%9}, {%0,%1,%2,%3};"
        : "+f"(c[0]),"+f"(c[1]),"+f"(c[2]),"+f"(c[3])
        : "r"(a[0]),"r"(a[1]),"r"(a[2]),"r"(a[3]), "r"(b[0]),"r"(b[1]));
}

// A-style tile: 128 rows x 32 halves, 80B row stride
__device__ __forceinline__ void fill_a(uint32_t dst, const half_t* g, int ld, int k0, int tid){
#pragma unroll
    for(int i=0;i<2;i++){
        int c = tid + i*256;
        int r = c>>2, ch = c&3;
        cpa(dst + r*80 + ch*16, (const char*)(g + (size_t)r*ld + k0) + ch*16);
    }
}
// TRB tile: 32 k-rows x 128 halves, 272B row stride; g pre-offset by n0
__device__ __forceinline__ void fill_bt(uint32_t dst, const half_t* g, int ld, int k0, int tid){
#pragma unroll
    for(int i=0;i<2;i++){
        int c = tid + i*256;
        int r = c>>4, ch = c&15;
        cpa(dst + r*272 + ch*16, (const char*)(g + (size_t)(k0+r)*ld) + ch*16);
    }
}

// ---------------- core mma.sync GEMM: C[128x128] tile ----------------------
// A row-major [M,K]; B: TRB? [K,N] natural (ldb = N row stride) : [N,K] (ldb = K row stride).
// 256 threads, 8 warps 2(m) x 4(n), warp tile 64x32.
// EPI: 0=fp32 C; 1=fp16 C.  STATS: also emit per-column online (max,sum) over
// this CTA's 128 rows into part[n0..n0+127] (softmax-over-rows partials).
template<int EPI,bool RELU,bool BIAS,bool TRB,bool STATS>
__device__ __forceinline__ void mm(
    const half_t* __restrict__ A,int lda,
    const half_t* __restrict__ B,int ldb,
    const float* __restrict__ bias,float alpha,
    float* __restrict__ C, half_t* __restrict__ Ch, long ldc,
    int K,int m0,int n0, float2* __restrict__ part)
{
    extern __shared__ __align__(16) char smem[];   // 3 stages x 20480
    uint32_t sb = s2u(smem);
    const int tid = threadIdx.x, lane = tid & 31, wid = tid >> 5;
    const int wm = wid & 1, wn = wid >> 1;

    A += (size_t)m0 * lda;
    B += TRB ? (size_t)n0 : (size_t)n0 * ldb;

    float acc[4][4][4];
#pragma unroll
    for(int i=0;i<4;i++)
#pragma unroll
        for(int j=0;j<4;j++)
#pragma unroll
            for(int q=0;q<4;q++) acc[i][j][q]=0.f;

    const int num = K >> 5;
    // prologue: stages 0,1
    fill_a(sb, A, lda, 0, tid);
    if(TRB) fill_bt(sb+10240, B, ldb, 0, tid);
    else    fill_a (sb+10240, B, ldb, 0, tid);
    CP_COMMIT();
    if(num>1){
        fill_a(sb+20480, A, lda, 32, tid);
        if(TRB) fill_bt(sb+30720, B, ldb, 32, tid);
        else    fill_a (sb+30720, B, ldb, 32, tid);
    }
    CP_COMMIT();

    const uint32_t a_base = (uint32_t)((wm*64 + (lane&15))*80 + (lane>>4)*16);
    const uint32_t b_base  = (uint32_t)((wn*32 + (lane&7) + ((lane>>4)<<3))*80 + ((lane>>3)&1)*16);
    const uint32_t bt_row  = (uint32_t)(((lane>>3)&1)*8 + (lane&7));
    const uint32_t bt_col  = (uint32_t)(wn*32 + ((lane>>4)<<3));

    for(int c=0;c<num;c++){
        if(c+1<num) cp_w1(); else cp_w0();
        __syncthreads();
        if(c+2<num){
            uint32_t nb = sb + (uint32_t)((c+2)%3)*20480;
            int k1 = (c+2) << 5;
            fill_a(nb, A, lda, k1, tid);
            if(TRB) fill_bt(nb+10240, B, ldb, k1, tid);
            else    fill_a (nb+10240, B, ldb, k1, tid);
        }
        CP_COMMIT();

        uint32_t st = sb + (uint32_t)(c%3)*20480;
        uint32_t aoff = st + a_base;
#pragma unroll
        for(int ks=0;ks<2;ks++){
            uint32_t af[4][4], bf[4][2], bt[4];
#pragma unroll
            for(int mf=0;mf<4;mf++) ldm4(af[mf], aoff + mf*1280 + ks*32);
            if(TRB){
                uint32_t bo = st + 10240 + (ks*16 + bt_row)*272 + bt_col*2;
                ldm4t(bt, bo);
                bf[0][0]=bt[0]; bf[0][1]=bt[1]; bf[1][0]=bt[2]; bf[1][1]=bt[3];
                ldm4t(bt, bo + 32);   // +16 n-cols
                bf[2][0]=bt[0]; bf[2][1]=bt[1]; bf[3][0]=bt[2]; bf[3][1]=bt[3];
            } else {
                uint32_t bo = st + 10240 + b_base;
                ldm4(bt, bo + ks*32);
                bf[0][0]=bt[0]; bf[0][1]=bt[1]; bf[1][0]=bt[2]; bf[1][1]=bt[3];
                ldm4(bt, bo + 1280 + ks*32);
                bf[2][0]=bt[0]; bf[2][1]=bt[1]; bf[3][0]=bt[2]; bf[3][1]=bt[3];
            }
#pragma unroll
            for(int mf=0;mf<4;mf++)
#pragma unroll
                for(int nf=0;nf<4;nf++) mma16816(acc[mf][nf], af[mf], bf[nf]);
        }
        // no second __syncthreads — next iter's top barrier precedes refill
    }

    // epilogue: write C
#pragma unroll
    for(int mf=0;mf<4;mf++){
#pragma unroll
        for(int nf=0;nf<4;nf++){
            int r  = m0 + wm*64 + mf*16 + (lane>>2);
            int cc = n0 + wn*32 + nf*8  + (lane&3)*2;
            float v0=acc[mf][nf][0]*alpha, v1=acc[mf][nf][1]*alpha;
            float v2=acc[mf][nf][2]*alpha, v3=acc[mf][nf][3]*alpha;
            if(BIAS){ float b0=bias[cc], b1=bias[cc+1]; v0+=b0; v1+=b1; v2+=b0; v3+=b1; }
            if(RELU){ v0=fmaxf(v0,0.f); v1=fmaxf(v1,0.f); v2=fmaxf(v2,0.f); v3=fmaxf(v3,0.f); }
            if(EPI==0){
                *(float2*)(C + (size_t)r*ldc + cc)     = make_float2(v0,v1);
                *(float2*)(C + (size_t)(r+8)*ldc + cc) = make_float2(v2,v3);
            } else {
                *(__half2*)(Ch + (size_t)r*ldc + cc)     = __floats2half2_rn(v0,v1);
                *(__half2*)(Ch + (size_t)(r+8)*ldc + cc) = __floats2half2_rn(v2,v3);
            }
        }
    }

    if(STATS){
        // column-wise online (max,sum) over this CTA's 128 rows.
        __syncthreads();                       // smem free after mainloop
        float2* st2 = (float2*)smem;           // [2][128]
        float sm_[4][2], ss_[4][2];
#pragma unroll
        for(int nf=0;nf<4;nf++){
#pragma unroll
            for(int j=0;j<2;j++){
                float m=-1e30f,s=0.f;
#pragma unroll
                for(int mf=0;mf<4;mf++){
#pragma unroll
                    for(int h=0;h<2;h++){
                        float v=acc[mf][nf][j+2*h]*alpha;
                        float nm=fmaxf(m,v);
                        s=s*__expf(m-nm)+__expf(v-nm); m=nm;
                    }
                }
                sm_[nf][j]=m; ss_[nf][j]=s;
            }
        }
        // merge the 8 row-groups within the warp (lane bits 2..4), col in lane&3
#pragma unroll
        for(int nf=0;nf<4;nf++){
#pragma unroll
            for(int j=0;j<2;j++){
                float m=sm_[nf][j], s=ss_[nf][j];
#pragma unroll
                for(int o=4;o<=16;o<<=1){
                    float om=__shfl_xor_sync(0xffffffffu,m,o);
                    float os=__shfl_xor_sync(0xffffffffu,s,o);
                    float nm=fmaxf(m,om);
                    s=s*__expf(m-nm)+os*__expf(om-nm); m=nm;
                }
                if((lane>>2)==0)
                    st2[wm*128 + wn*32 + nf*8 + (lane&3)*2 + j]=make_float2(m,s);
            }
        }
        __syncthreads();
        if(tid<128){
            float2 a0=st2[tid], a1=st2[128+tid];
            float nm=fmaxf(a0.x,a1.x);
            float s=a0.y*__expf(a0.x-nm)+a1.y*__expf(a1.x-nm);
            part[n0+tid]=make_float2(nm,s);
        }
    }
}

#define SMB (3*20480)

// ---------------- GEMM wrapper kernels ----------------
// fused QKV projection: grid (8, 3, 32); y: 0=Q (input xq), 1=K, 2=V (input xkv)
__global__ void __launch_bounds__(256)
k_proj3(const half_t* xq,const half_t* xkv,const half_t* w,
        const float* bq,const float* bk,const float* bv,
        half_t* oq,half_t* ok,half_t* ov){
    int which=blockIdx.y;
    int z=blockIdx.z,b=z>>4,h=z&15;
    const half_t* A = (which==0)?xq:xkv;
    const float* bias = (which==0)?bq:((which==1)?bk:bv);
    half_t* o = (which==0)?oq:((which==1)?ok:ov);
    mm<1,false,true,true,false>(A+(size_t)b*Sz*Dz,Dz,
        w+(size_t)which*NW_H+(size_t)h*Dz*DHz,DHz,
        bias+h*DHz,1.0f, nullptr,o+(size_t)z*Sz*DHz,DHz, Dz, blockIdx.x*128,0, nullptr);
}
// scores + fused per-tile softmax stats
__global__ void __launch_bounds__(256)
k_scores(const half_t* q,const half_t* k,float* sc,float2* part){
    size_t z=blockIdx.z;
    mm<0,false,false,false,true>(q+z*Sz*DHz,DHz, k+z*Sz*DHz,DHz,
        nullptr,0.08838834764831845f, sc+z*Sz*Sz,nullptr,Sz, DHz,
        blockIdx.x*128, blockIdx.y*128,
        part + ((size_t)z*8 + blockIdx.x)*Sz);
}
__global__ void __launch_bounds__(256)
k_attnv(const half_t* a,const half_t* v,half_t* cat){
    size_t z=blockIdx.z; int b=blockIdx.z>>4,h=blockIdx.z&15;
    mm<1,false,false,true,false>(a+z*Sz*Sz,Sz, v+z*Sz*DHz,DHz,
        nullptr,1.0f, nullptr,cat+(size_t)b*Sz*Dz+h*DHz,Dz, Sz, blockIdx.x*128,0, nullptr);
}
__global__ void __launch_bounds__(256)
k_lin32(const half_t* a,int lda,const half_t* b,int ldb,
        const float* bias,float* C,int ldc,int K){
    mm<0,false,true,true,false>(a,lda,b,ldb,bias,1.0f,C,nullptr,ldc,K,
        blockIdx.x*128, blockIdx.y*128, nullptr);
}
__global__ void __launch_bounds__(256)
k_linrelu(const half_t* a,int lda,const half_t* b,int ldb,
          const float* bias,half_t* Ch,int ldc,int K){
    mm<1,true,true,true,false>(a,lda,b,ldb,bias,1.0f,nullptr,Ch,ldc,K,
        blockIdx.x*128, blockIdx.y*128, nullptr);
}

// ---------------- conversions (single launch) ----------------
struct CvtArgs {
    const float4* in[12];
    __half2* out[12];
    int n4[12];
};
__global__ void __launch_bounds__(256)
k_hall(CvtArgs a){
    int seg = blockIdx.y;
    const float4* in = a.in[seg];
    __half2* o = a.out[seg];
    int n4 = a.n4[seg];
    for(int i=blockIdx.x*256+threadIdx.x; i<n4; i+=gridDim.x*256){
        float4 v=in[i];
        o[2*i]   = __floats2half2_rn(v.x,v.y);
        o[2*i+1] = __floats2half2_rn(v.z,v.w);
    }
}

// ---------------- softmax normalize: parallel, register-resident stats -----
// grid (32, 32): CTA = 32-row chunk of one z; thread owns 4 columns.
__global__ void __launch_bounds__(256)
k_smnorm(const float* __restrict__ sc, const float2* __restrict__ part,
         half_t* __restrict__ o){
    int z=blockIdx.y, rc=blockIdx.x;
    int c0=threadIdx.x*4;
    float m[4], inv[4];
#pragma unroll
    for(int j=0;j<4;j++){
        float mm=-1e30f,s=0.f;
#pragma unroll
        for(int k=0;k<8;k++){
            float2 ps=part[((size_t)z*8+k)*Sz+c0+j];
            float nm=fmaxf(mm,ps.x);
            s=s*__expf(mm-nm)+ps.y*__expf(ps.x-nm);
            mm=nm;
        }
        m[j]=mm; inv[j]=1.0f/s;
    }
    size_t base=(size_t)z*Sz*Sz+(size_t)rc*32*Sz+c0;
#pragma unroll 4
    for(int r=0;r<32;r++){
        size_t ro=base+(size_t)r*Sz;
        float4 v=*(const float4*)(sc+ro);
        __half2 h0=__floats2half2_rn(__expf(v.x-m[0])*inv[0], __expf(v.y-m[1])*inv[1]);
        __half2 h1=__floats2half2_rn(__expf(v.z-m[2])*inv[2], __expf(v.w-m[3])*inv[3]);
        uint2 w;
        w.x=*(uint32_t*)&h0; w.y=*(uint32_t*)&h1;
        *(uint2*)(o+ro)=w;
    }
}

__global__ void __launch_bounds__(256)
k_addln(const float* __restrict__ xa,const float* __restrict__ xb,
        const float* __restrict__ gg,const float* __restrict__ bb,
        float* __restrict__ out, half_t* __restrict__ oh){
    int row=blockIdx.x;
    const float* xr=xa+(size_t)row*Dz;
    const float* yr=xb+(size_t)row*Dz;
    float v[8]; float s=0.f,s2=0.f;
#pragma unroll
    for(int i=0;i<8;i++){ int c=threadIdx.x+i*256; v[i]=xr[c]+yr[c]; s+=v[i]; s2+=v[i]*v[i]; }
    __shared__ float rs[8],rs2[8];
#pragma unroll
    for(int o=16;o>0;o>>=1){ s+=__shfl_xor_sync(0xffffffffu,s,o); s2+=__shfl_xor_sync(0xffffffffu,s2,o); }
    int wid=threadIdx.x>>5,lid=threadIdx.x&31;
    if(lid==0){ rs[wid]=s; rs2[wid]=s2; }
    __syncthreads();
    if(threadIdx.x<32){
        s=(threadIdx.x<8)?rs[threadIdx.x]:0.f; s2=(threadIdx.x<8)?rs2[threadIdx.x]:0.f;
#pragma unroll
        for(int o=4;o>0;o>>=1){ s+=__shfl_xor_sync(0xffffffffu,s,o); s2+=__shfl_xor_sync(0xffffffffu,s2,o); }
        if(threadIdx.x==0){ rs[0]=s; rs2[0]=s2; }
    }
    __syncthreads();
    float mean=rs[0]*(1.0f/Dz);
    float var=rs2[0]*(1.0f/Dz)-mean*mean;
    float inv=rsqrtf(var+1e-5f);
#pragma unroll
    for(int i=0;i<8;i++){
        int c=threadIdx.x+i*256;
        float o=(v[i]-mean)*inv*gg[c]+bb[c];
        out[(size_t)row*Dz+c]=o;
        if(oh) oh[(size_t)row*Dz+c]=__float2half_rn(o);
    }
}

// ---------------- launch ----------------
#define GA(v,s) do{ void* _p; cudaGetSymbolAddress(&_p,s); v=(decltype(v))_p; }while(0)

extern "C" void kernel_launch(void* const* d_in,const int* in_sizes,int n_in,
                              void* d_out,int out_size)
{
    const float* x   =(const float*)d_in[0];
    const float* enc =(const float*)d_in[1];
    const float* wq1 =(const float*)d_in[2];
    const float* wk1 =(const float*)d_in[3];
    const float* wv1 =(const float*)d_in[4];
    const float* bq1 =(const float*)d_in[5];
    const float* bk1 =(const float*)d_in[6];
    const float* bv1 =(const float*)d_in[7];
    const float* wp1 =(const float*)d_in[8];
    const float* bp1 =(const float*)d_in[9];
    const float* wq2 =(const float*)d_in[10];
    const float* wk2 =(const float*)d_in[11];
    const float* wv2 =(const float*)d_in[12];
    const float* bq2 =(const float*)d_in[13];
    const float* bk2 =(const float*)d_in[14];
    const float* bv2 =(const float*)d_in[15];
    const float* wp2 =(const float*)d_in[16];
    const float* bp2 =(const float*)d_in[17];
    const float* ln1g=(const float*)d_in[18];
    const float* ln1b=(const float*)d_in[19];
    const float* ln2g=(const float*)d_in[20];
    const float* ln2b=(const float*)d_in[21];
    const float* ln3g=(const float*)d_in[22];
    const float* ln3b=(const float*)d_in[23];
    const float* wff1=(const float*)d_in[24];
    const float* bff1=(const float*)d_in[25];
    const float* wff2=(const float*)d_in[26];
    const float* bff2=(const float*)d_in[27];
    float* out=(float*)d_out;

    float *sc,*tp,*r1,*r2; float2* part;
    half_t *xh,*eh,*h1,*h2,*qh,*kh,*vh,*ah,*ch,*fh,*w1,*w2,*pc,*Fc;
    GA(sc,g_sc); GA(tp,g_t); GA(r1,g_r1); GA(r2,g_r2); GA(part,g_part);
    GA(xh,g_xh); GA(eh,g_eh); GA(h1,g_1h); GA(h2,g_2h);
    GA(qh,g_qh); GA(kh,g_kh); GA(vh,g_vh); GA(ah,g_ah);
    GA(ch,g_ch); GA(fh,g_fh);
    GA(w1,g_w1c); GA(w2,g_w2c); GA(pc,g_pc); GA(Fc,g_Fc);

    cudaFuncSetAttribute(k_proj3,  cudaFuncAttributeMaxDynamicSharedMemorySize,SMB);
    cudaFuncSetAttribute(k_scores, cudaFuncAttributeMaxDynamicSharedMemorySize,SMB);
    cudaFuncSetAttribute(k_attnv,  cudaFuncAttributeMaxDynamicSharedMemorySize,SMB);
    cudaFuncSetAttribute(k_lin32,  cudaFuncAttributeMaxDynamicSharedMemorySize,SMB);
    cudaFuncSetAttribute(k_linrelu,cudaFuncAttributeMaxDynamicSharedMemorySize,SMB);

    // all fp32->fp16 casts in ONE launch
    CvtArgs ca;
    ca.in[0]=(const float4*)wq1;  ca.out[0]=(__half2*)w1;           ca.n4[0]=NW_H/4;
    ca.in[1]=(const float4*)wk1;  ca.out[1]=(__half2*)(w1+NW_H);    ca.n4[1]=NW_H/4;
    ca.in[2]=(const float4*)wv1;  ca.out[2]=(__half2*)(w1+2*NW_H);  ca.n4[2]=NW_H/4;
    ca.in[3]=(const float4*)wq2;  ca.out[3]=(__half2*)w2;           ca.n4[3]=NW_H/4;
    ca.in[4]=(const float4*)wk2;  ca.out[4]=(__half2*)(w2+NW_H);    ca.n4[4]=NW_H/4;
    ca.in[5]=(const float4*)wv2;  ca.out[5]=(__half2*)(w2+2*NW_H);  ca.n4[5]=NW_H/4;
    ca.in[6]=(const float4*)wp1;  ca.out[6]=(__half2*)pc;           ca.n4[6]=NW_P/4;
    ca.in[7]=(const float4*)wp2;  ca.out[7]=(__half2*)(pc+NW_P);    ca.n4[7]=NW_P/4;
    ca.in[8]=(const float4*)wff1; ca.out[8]=(__half2*)Fc;           ca.n4[8]=NW_F/4;
    ca.in[9]=(const float4*)wff2; ca.out[9]=(__half2*)(Fc+NW_F);    ca.n4[9]=NW_F/4;
    ca.in[10]=(const float4*)x;   ca.out[10]=(__half2*)xh;          ca.n4[10]=NX/4;
    ca.in[11]=(const float4*)enc; ca.out[11]=(__half2*)eh;          ca.n4[11]=NX/4;
    k_hall<<<dim3(512,12),256>>>(ca);

    dim3 gp3(Sz/128,3,Bz*Hz), gp(Sz/128,1,Bz*Hz), gs(Sz/128,Sz/128,Bz*Hz);
    dim3 gsm(32,Bz*Hz);
    dim3 gpp(2*Sz/128,Dz/128), gf1(2*Sz/128,DFFz/128);

    // ---- self attention ----
    k_proj3<<<gp3,256,SMB>>>(xh,xh,w1,bq1,bk1,bv1,qh,kh,vh);
    k_scores<<<gs,256,SMB>>>(qh,kh,sc,part);
    k_smnorm<<<gsm,256>>>(sc,part,ah);
    k_attnv<<<gp,256,SMB>>>(ah,vh,ch);
    k_lin32<<<gpp,256,SMB>>>(ch,Dz,pc,Dz,bp1,tp,Dz,Dz);
    k_addln<<<Bz*Sz,256>>>(x,tp,ln1g,ln1b,r1,h1);

    // ---- cross attention: q from encoder_output, k/v from x1 ----
    k_proj3<<<gp3,256,SMB>>>(eh,h1,w2,bq2,bk2,bv2,qh,kh,vh);
    k_scores<<<gs,256,SMB>>>(qh,kh,sc,part);
    k_smnorm<<<gsm,256>>>(sc,part,ah);
    k_attnv<<<gp,256,SMB>>>(ah,vh,ch);
    k_lin32<<<gpp,256,SMB>>>(ch,Dz,pc+NW_P,Dz,bp2,tp,Dz,Dz);
    k_addln<<<Bz*Sz,256>>>(r1,tp,ln2g,ln2b,r2,h2);

    // ---- feed forward (ldb = natural row stride of B: wff1->DFFz, wff2->Dz) ----
    k_linrelu<<<gf1,256,SMB>>>(h2,Dz,Fc,DFFz,bff1,fh,DFFz,Dz);
    k_lin32<<<gpp,256,SMB>>>(fh,DFFz,Fc+NW_F,Dz,bff2,tp,Dz,DFFz);
    k_addln<<<Bz*Sz,256>>>(r2,tp,ln3g,ln3b,out,nullptr);
}